// round 7
// baseline (speedup 1.0000x reference)
#include <cuda_runtime.h>

// MyModel_83597243450144 : 4-layer LSTM autoencoder, fp32 with packed f32x2 FMA.
// B=2048, T=128, H1=128, H2=64. Gate order i,f,g,o; g uses relu, h = o*relu(c).
//
// Layout tricks (all to feed fma.rn.f32x2 / FFMA2 with zero per-iter packing):
//  - weights packed [k][u][i,f,g,o] -> one LDG.128 = two f32x2 regs (w_if, w_go)
//  - hidden state / x duplicated in shared (h,h) -> one LDS.128 = two dup f32x2
//  - accumulators pair gates: a_if = (z_i,z_f), a_go = (z_g,z_o)

#define B_ALL 2048
#define T_SEQ 128
#define BT 16
#define NBLK (B_ALL / BT)  // 128 CTAs
#define HROW 36            // shared row stride in floats (32 dup data + 4 pad), 16B-mult

typedef unsigned long long ull;

// ---- device scratch (no allocations allowed) ----
__device__ float g_U1p[128 * 512];   // [k][u*4+g]  (U1 repacked)
__device__ float g_WU2p[192 * 256];  // k<128: W2, k>=128: U2
__device__ float g_W3p[64 * 256];
__device__ float g_U3p[64 * 256];
__device__ float g_WU4p[192 * 512];  // k<64: W4, k>=64: U4
__device__ float g_h2last[B_ALL * 64];

__device__ __forceinline__ float sigmoidf_(float v) {
    return __fdividef(1.0f, 1.0f + __expf(-v));
}
__device__ __forceinline__ ull pack2_(float lo, float hi) {
    ull r;
    asm("mov.b64 %0, {%1, %2};" : "=l"(r) : "f"(lo), "f"(hi));
    return r;
}
__device__ __forceinline__ void unpack2_(ull v, float& lo, float& hi) {
    asm("mov.b64 {%0, %1}, %2;" : "=f"(lo), "=f"(hi) : "l"(v));
}
__device__ __forceinline__ ull fma2_(ull a, ull b, ull c) {
    ull d;
    asm("fma.rn.f32x2 %0, %1, %2, %3;" : "=l"(d) : "l"(a), "l"(b), "l"(c));
    return d;
}

// ---------------------------------------------------------------------------
// Weight repack: per hidden unit u, the 4 gate weights (i,f,g,o) contiguous.
// Total elements = 65536 + 49152 + 16384 + 16384 + 98304 = 245760 = 960*256.
// ---------------------------------------------------------------------------
__global__ void pack_kernel(const float* __restrict__ U1,
                            const float* __restrict__ W2, const float* __restrict__ U2,
                            const float* __restrict__ W3, const float* __restrict__ U3,
                            const float* __restrict__ W4, const float* __restrict__ U4) {
    int e = blockIdx.x * blockDim.x + threadIdx.x;
    if (e < 65536) {  // U1p: [128][512]
        int k = e >> 9, r = e & 511, u = r >> 2, g = r & 3;
        g_U1p[e] = U1[k * 512 + g * 128 + u];
        return;
    }
    int e2 = e - 65536;
    if (e2 < 49152) {  // WU2p: [192][256]
        int k = e2 >> 8, r = e2 & 255, u = r >> 2, g = r & 3;
        g_WU2p[e2] = (k < 128) ? W2[k * 256 + g * 64 + u]
                               : U2[(k - 128) * 256 + g * 64 + u];
        return;
    }
    int e3 = e2 - 49152;
    if (e3 < 16384) {  // W3p: [64][256]
        int k = e3 >> 8, r = e3 & 255, u = r >> 2, g = r & 3;
        g_W3p[e3] = W3[k * 256 + g * 64 + u];
        return;
    }
    int e4 = e3 - 16384;
    if (e4 < 16384) {  // U3p: [64][256]
        int k = e4 >> 8, r = e4 & 255, u = r >> 2, g = r & 3;
        g_U3p[e4] = U3[k * 256 + g * 64 + u];
        return;
    }
    int e5 = e4 - 16384;
    if (e5 < 98304) {  // WU4p: [192][512]
        int k = e5 >> 9, r = e5 & 511, u = r >> 2, g = r & 3;
        g_WU4p[e5] = (k < 64) ? W4[k * 512 + g * 128 + u]
                              : U4[(k - 64) * 512 + g * 128 + u];
    }
}

// ---------------------------------------------------------------------------
// Phase A: LSTM1 (H=128) + LSTM2 (H=64), 16 samples per CTA.
// hcat rows 0..127 = h1, rows 128..191 = h2; each value duplicated (h,h).
// ---------------------------------------------------------------------------
__global__ void __launch_bounds__(256, 1)
phaseA_kernel(const float* __restrict__ x, const float* __restrict__ W1,
              const float* __restrict__ b1, const float* __restrict__ b2) {
    __shared__ float hcat[192 * HROW];
    __shared__ float xs[T_SEQ * 32];  // duplicated x: [t][2b],[t][2b+1]

    const int tid = threadIdx.x;
    const int b0 = blockIdx.x * BT;

    for (int i = tid; i < T_SEQ * BT; i += 256) {
        int b = i >> 7, t = i & 127;
        float v = x[(b0 + b) * T_SEQ + t];
        xs[t * 32 + 2 * b]     = v;
        xs[t * 32 + 2 * b + 1] = v;
    }
    for (int i = tid; i < 192 * HROW; i += 256) hcat[i] = 0.0f;

    const int u1 = tid & 127, bg1 = tid >> 7;  // 8 samples each
    const int u2 = tid & 63,  bg2 = tid >> 6;  // 4 samples each

    const ulonglong2* __restrict__ U1p2  = (const ulonglong2*)g_U1p;   // [k*128+u1]
    const ulonglong2* __restrict__ WU2p2 = (const ulonglong2*)g_WU2p;  // [k*64 +u2]

    const ull w1if = pack2_(W1[u1], W1[128 + u1]);
    const ull w1go = pack2_(W1[256 + u1], W1[384 + u1]);
    const ull b1if = pack2_(b1[u1], b1[128 + u1]);
    const ull b1go = pack2_(b1[256 + u1], b1[384 + u1]);
    const ull b2if = pack2_(b2[u2], b2[64 + u2]);
    const ull b2go = pack2_(b2[128 + u2], b2[192 + u2]);

    float c1[8], c2[4];
#pragma unroll
    for (int j = 0; j < 8; j++) c1[j] = 0.0f;
#pragma unroll
    for (int j = 0; j < 4; j++) c2[j] = 0.0f;

    __syncthreads();

    for (int t = 0; t < T_SEQ; t++) {
        // ---- layer 1: z1 = x_t*W1 + h1 @ U1 + b1 ----
        ull aif[8], ago[8];
        {
            const float* xp = xs + t * 32 + bg1 * 16;
#pragma unroll
            for (int q = 0; q < 4; q++) {
                ulonglong2 xd = *(const ulonglong2*)(xp + 4 * q);
                aif[2 * q]     = fma2_(xd.x, w1if, b1if);
                ago[2 * q]     = fma2_(xd.x, w1go, b1go);
                aif[2 * q + 1] = fma2_(xd.y, w1if, b1if);
                ago[2 * q + 1] = fma2_(xd.y, w1go, b1go);
            }
        }
        const float* hp = hcat + bg1 * 16;
#pragma unroll 4
        for (int k = 0; k < 128; k++) {
            ulonglong2 w = U1p2[k * 128 + u1];
            ulonglong2 h0 = *(const ulonglong2*)(hp + k * HROW);
            ulonglong2 h1 = *(const ulonglong2*)(hp + k * HROW + 4);
            ulonglong2 h2 = *(const ulonglong2*)(hp + k * HROW + 8);
            ulonglong2 h3 = *(const ulonglong2*)(hp + k * HROW + 12);
            ull hv[8] = {h0.x, h0.y, h1.x, h1.y, h2.x, h2.y, h3.x, h3.y};
#pragma unroll
            for (int j = 0; j < 8; j++) {
                aif[j] = fma2_(hv[j], w.x, aif[j]);
                ago[j] = fma2_(hv[j], w.y, ago[j]);
            }
        }
        __syncthreads();  // all reads of old h1 complete
#pragma unroll
        for (int j = 0; j < 8; j++) {
            float zi, zf, zg, zo;
            unpack2_(aif[j], zi, zf);
            unpack2_(ago[j], zg, zo);
            float iv = sigmoidf_(zi);
            float fv = sigmoidf_(zf);
            float gv = fmaxf(zg, 0.0f);
            float ov = sigmoidf_(zo);
            float c  = fmaf(fv, c1[j], iv * gv);
            c1[j] = c;
            float h = ov * fmaxf(c, 0.0f);
            *(float2*)&hcat[u1 * HROW + bg1 * 16 + 2 * j] = make_float2(h, h);
        }
        __syncthreads();  // new h1 visible

        // ---- layer 2: z2 = h1_t @ W2 + h2 @ U2 + b2 (single K=192 loop) ----
        ull a2if[4], a2go[4];
#pragma unroll
        for (int j = 0; j < 4; j++) { a2if[j] = b2if; a2go[j] = b2go; }
        const float* hp2 = hcat + bg2 * 8;
#pragma unroll 4
        for (int k = 0; k < 192; k++) {
            ulonglong2 w = WU2p2[k * 64 + u2];
            ulonglong2 h0 = *(const ulonglong2*)(hp2 + k * HROW);
            ulonglong2 h1 = *(const ulonglong2*)(hp2 + k * HROW + 4);
            ull hv[4] = {h0.x, h0.y, h1.x, h1.y};
#pragma unroll
            for (int j = 0; j < 4; j++) {
                a2if[j] = fma2_(hv[j], w.x, a2if[j]);
                a2go[j] = fma2_(hv[j], w.y, a2go[j]);
            }
        }
        __syncthreads();  // all reads of old h2 complete
#pragma unroll
        for (int j = 0; j < 4; j++) {
            float zi, zf, zg, zo;
            unpack2_(a2if[j], zi, zf);
            unpack2_(a2go[j], zg, zo);
            float iv = sigmoidf_(zi);
            float fv = sigmoidf_(zf);
            float gv = fmaxf(zg, 0.0f);
            float ov = sigmoidf_(zo);
            float c  = fmaf(fv, c2[j], iv * gv);
            c2[j] = c;
            float h = ov * fmaxf(c, 0.0f);
            *(float2*)&hcat[(128 + u2) * HROW + bg2 * 8 + 2 * j] = make_float2(h, h);
            if (t == T_SEQ - 1) g_h2last[(b0 + bg2 * 4 + j) * 64 + u2] = h;
        }
        // next-iteration layer-1 pass only touches rows <128; the two barriers
        // above separate this write from the next read of rows >=128.
    }
}

// ---------------------------------------------------------------------------
// Phase B: RepeatVector(h2_last) -> LSTM3 (H=64) -> LSTM4 (H=128) -> Dense(1).
// hcat rows 0..63 = h3, rows 64..191 = h4 (duplicated values).
// Layer-3 input path (h2_last @ W3 + b3) is constant over t -> held in regs.
// ---------------------------------------------------------------------------
__global__ void __launch_bounds__(256, 1)
phaseB_kernel(const float* __restrict__ b3, const float* __restrict__ b4,
              const float* __restrict__ Wd, const float* __restrict__ bd,
              float* __restrict__ out) {
    __shared__ float hcat[192 * HROW];
    __shared__ float h2T[64 * 32];  // duplicated: [k][2b],[k][2b+1]

    const int tid = threadIdx.x;
    const int b0 = blockIdx.x * BT;

    for (int i = tid; i < 64 * BT; i += 256) {
        int b = i >> 6, k = i & 63;
        float v = g_h2last[(b0 + b) * 64 + k];
        h2T[k * 32 + 2 * b]     = v;
        h2T[k * 32 + 2 * b + 1] = v;
    }
    for (int i = tid; i < 192 * HROW; i += 256) hcat[i] = 0.0f;

    const int u3 = tid & 63,  bg  = tid >> 6;  // 4 samples
    const int u4 = tid & 127, bg2 = tid >> 7;  // 8 samples
    const int lane16 = tid & 15, bq = tid >> 4;

    const ulonglong2* __restrict__ W3p2  = (const ulonglong2*)g_W3p;
    const ulonglong2* __restrict__ U3p2  = (const ulonglong2*)g_U3p;
    const ulonglong2* __restrict__ WU4p2 = (const ulonglong2*)g_WU4p;

    const ull b4if = pack2_(b4[u4], b4[128 + u4]);
    const ull b4go = pack2_(b4[256 + u4], b4[384 + u4]);
    float wd[8];
#pragma unroll
    for (int r = 0; r < 8; r++) wd[r] = Wd[lane16 + 16 * r];
    const float bdv = bd[0];

    __syncthreads();

    // precompute zx3 = h2_last @ W3 + b3 (constant over t) into registers
    ull zif[4], zgo[4];
    {
        const ull b3if = pack2_(b3[u3], b3[64 + u3]);
        const ull b3go = pack2_(b3[128 + u3], b3[192 + u3]);
#pragma unroll
        for (int j = 0; j < 4; j++) { zif[j] = b3if; zgo[j] = b3go; }
        const float* hpx = h2T + bg * 8;
#pragma unroll 4
        for (int k = 0; k < 64; k++) {
            ulonglong2 w = W3p2[k * 64 + u3];
            ulonglong2 h0 = *(const ulonglong2*)(hpx + k * 32);
            ulonglong2 h1 = *(const ulonglong2*)(hpx + k * 32 + 4);
            ull hv[4] = {h0.x, h0.y, h1.x, h1.y};
#pragma unroll
            for (int j = 0; j < 4; j++) {
                zif[j] = fma2_(hv[j], w.x, zif[j]);
                zgo[j] = fma2_(hv[j], w.y, zgo[j]);
            }
        }
    }

    float c3[4], c4[8];
#pragma unroll
    for (int j = 0; j < 4; j++) c3[j] = 0.0f;
#pragma unroll
    for (int j = 0; j < 8; j++) c4[j] = 0.0f;

    for (int t = 0; t < T_SEQ; t++) {
        // ---- layer 3: z3 = zx3 + h3 @ U3 ----
        ull a3if[4], a3go[4];
#pragma unroll
        for (int j = 0; j < 4; j++) { a3if[j] = zif[j]; a3go[j] = zgo[j]; }
        const float* hp3 = hcat + bg * 8;
#pragma unroll 4
        for (int k = 0; k < 64; k++) {
            ulonglong2 w = U3p2[k * 64 + u3];
            ulonglong2 h0 = *(const ulonglong2*)(hp3 + k * HROW);
            ulonglong2 h1 = *(const ulonglong2*)(hp3 + k * HROW + 4);
            ull hv[4] = {h0.x, h0.y, h1.x, h1.y};
#pragma unroll
            for (int j = 0; j < 4; j++) {
                a3if[j] = fma2_(hv[j], w.x, a3if[j]);
                a3go[j] = fma2_(hv[j], w.y, a3go[j]);
            }
        }
        __syncthreads();
#pragma unroll
        for (int j = 0; j < 4; j++) {
            float zi, zf, zg, zo;
            unpack2_(a3if[j], zi, zf);
            unpack2_(a3go[j], zg, zo);
            float iv = sigmoidf_(zi);
            float fv = sigmoidf_(zf);
            float gv = fmaxf(zg, 0.0f);
            float ov = sigmoidf_(zo);
            float c  = fmaf(fv, c3[j], iv * gv);
            c3[j] = c;
            float h = ov * fmaxf(c, 0.0f);
            *(float2*)&hcat[u3 * HROW + bg * 8 + 2 * j] = make_float2(h, h);
        }
        __syncthreads();

        // ---- layer 4: z4 = h3_t @ W4 + h4 @ U4 + b4 (K=192) ----
        ull a4if[8], a4go[8];
#pragma unroll
        for (int j = 0; j < 8; j++) { a4if[j] = b4if; a4go[j] = b4go; }
        const float* hp4 = hcat + bg2 * 16;
#pragma unroll 4
        for (int k = 0; k < 192; k++) {
            ulonglong2 w = WU4p2[k * 128 + u4];
            ulonglong2 h0 = *(const ulonglong2*)(hp4 + k * HROW);
            ulonglong2 h1 = *(const ulonglong2*)(hp4 + k * HROW + 4);
            ulonglong2 h2 = *(const ulonglong2*)(hp4 + k * HROW + 8);
            ulonglong2 h3 = *(const ulonglong2*)(hp4 + k * HROW + 12);
            ull hv[8] = {h0.x, h0.y, h1.x, h1.y, h2.x, h2.y, h3.x, h3.y};
#pragma unroll
            for (int j = 0; j < 8; j++) {
                a4if[j] = fma2_(hv[j], w.x, a4if[j]);
                a4go[j] = fma2_(hv[j], w.y, a4go[j]);
            }
        }
        __syncthreads();
#pragma unroll
        for (int j = 0; j < 8; j++) {
            float zi, zf, zg, zo;
            unpack2_(a4if[j], zi, zf);
            unpack2_(a4go[j], zg, zo);
            float iv = sigmoidf_(zi);
            float fv = sigmoidf_(zf);
            float gv = fmaxf(zg, 0.0f);
            float ov = sigmoidf_(zo);
            float c  = fmaf(fv, c4[j], iv * gv);
            c4[j] = c;
            float h = ov * fmaxf(c, 0.0f);
            *(float2*)&hcat[(64 + u4) * HROW + bg2 * 16 + 2 * j] = make_float2(h, h);
        }
        __syncthreads();

        // ---- dense: out[b][t] = h4 . Wd + bd (16-lane tree per sample) ----
        float s = 0.0f;
#pragma unroll
        for (int r = 0; r < 8; r++)
            s = fmaf(hcat[(64 + lane16 + 16 * r) * HROW + bq * 2], wd[r], s);
        s += __shfl_xor_sync(0xffffffffu, s, 8);
        s += __shfl_xor_sync(0xffffffffu, s, 4);
        s += __shfl_xor_sync(0xffffffffu, s, 2);
        s += __shfl_xor_sync(0xffffffffu, s, 1);
        if (lane16 == 0) out[(b0 + bq) * T_SEQ + t] = s + bdv;
        // dense reads complete before the first barrier of the next iteration;
        // h4 rows are rewritten only after two more barriers.
    }
}

// ---------------------------------------------------------------------------
extern "C" void kernel_launch(void* const* d_in, const int* in_sizes, int n_in,
                              void* d_out, int out_size) {
    const float* x  = (const float*)d_in[0];
    const float* W1 = (const float*)d_in[1];
    const float* U1 = (const float*)d_in[2];
    const float* b1 = (const float*)d_in[3];
    const float* W2 = (const float*)d_in[4];
    const float* U2 = (const float*)d_in[5];
    const float* b2 = (const float*)d_in[6];
    const float* W3 = (const float*)d_in[7];
    const float* U3 = (const float*)d_in[8];
    const float* b3 = (const float*)d_in[9];
    const float* W4 = (const float*)d_in[10];
    const float* U4 = (const float*)d_in[11];
    const float* b4 = (const float*)d_in[12];
    const float* Wd = (const float*)d_in[13];
    const float* bd = (const float*)d_in[14];
    float* out = (float*)d_out;

    pack_kernel<<<960, 256>>>(U1, W2, U2, W3, U3, W4, U4);
    phaseA_kernel<<<NBLK, 256>>>(x, W1, b1, b2);
    phaseB_kernel<<<NBLK, 256>>>(b3, b4, Wd, bd, out);
}

// round 8
// speedup vs baseline: 1.0001x; 1.0001x over previous
#include <cuda_runtime.h>

// MyModel_83597243450144 : 4-layer LSTM autoencoder, fp32 with packed f32x2 FMA.
// B=2048, T=128, H1=128, H2=64. Gate order i,f,g,o; g uses relu, h = o*relu(c).
//
// Layout tricks (all to feed fma.rn.f32x2 / FFMA2 with zero per-iter packing):
//  - weights packed [k][u][i,f,g,o] -> one LDG.128 = two f32x2 regs (w_if, w_go)
//  - hidden state / x duplicated in shared (h,h) -> one LDS.128 = two dup f32x2
//  - accumulators pair gates: a_if = (z_i,z_f), a_go = (z_g,z_o)

#define B_ALL 2048
#define T_SEQ 128
#define BT 16
#define NBLK (B_ALL / BT)  // 128 CTAs
#define HROW 36            // shared row stride in floats (32 dup data + 4 pad), 16B-mult

typedef unsigned long long ull;

// ---- device scratch (no allocations allowed) ----
__device__ float g_U1p[128 * 512];   // [k][u*4+g]  (U1 repacked)
__device__ float g_WU2p[192 * 256];  // k<128: W2, k>=128: U2
__device__ float g_W3p[64 * 256];
__device__ float g_U3p[64 * 256];
__device__ float g_WU4p[192 * 512];  // k<64: W4, k>=64: U4
__device__ float g_h2last[B_ALL * 64];

__device__ __forceinline__ float sigmoidf_(float v) {
    return __fdividef(1.0f, 1.0f + __expf(-v));
}
__device__ __forceinline__ ull pack2_(float lo, float hi) {
    ull r;
    asm("mov.b64 %0, {%1, %2};" : "=l"(r) : "f"(lo), "f"(hi));
    return r;
}
__device__ __forceinline__ void unpack2_(ull v, float& lo, float& hi) {
    asm("mov.b64 {%0, %1}, %2;" : "=f"(lo), "=f"(hi) : "l"(v));
}
__device__ __forceinline__ ull fma2_(ull a, ull b, ull c) {
    ull d;
    asm("fma.rn.f32x2 %0, %1, %2, %3;" : "=l"(d) : "l"(a), "l"(b), "l"(c));
    return d;
}

// ---------------------------------------------------------------------------
// Weight repack: per hidden unit u, the 4 gate weights (i,f,g,o) contiguous.
// Total elements = 65536 + 49152 + 16384 + 16384 + 98304 = 245760 = 960*256.
// ---------------------------------------------------------------------------
__global__ void pack_kernel(const float* __restrict__ U1,
                            const float* __restrict__ W2, const float* __restrict__ U2,
                            const float* __restrict__ W3, const float* __restrict__ U3,
                            const float* __restrict__ W4, const float* __restrict__ U4) {
    int e = blockIdx.x * blockDim.x + threadIdx.x;
    if (e < 65536) {  // U1p: [128][512]
        int k = e >> 9, r = e & 511, u = r >> 2, g = r & 3;
        g_U1p[e] = U1[k * 512 + g * 128 + u];
        return;
    }
    int e2 = e - 65536;
    if (e2 < 49152) {  // WU2p: [192][256]
        int k = e2 >> 8, r = e2 & 255, u = r >> 2, g = r & 3;
        g_WU2p[e2] = (k < 128) ? W2[k * 256 + g * 64 + u]
                               : U2[(k - 128) * 256 + g * 64 + u];
        return;
    }
    int e3 = e2 - 49152;
    if (e3 < 16384) {  // W3p: [64][256]
        int k = e3 >> 8, r = e3 & 255, u = r >> 2, g = r & 3;
        g_W3p[e3] = W3[k * 256 + g * 64 + u];
        return;
    }
    int e4 = e3 - 16384;
    if (e4 < 16384) {  // U3p: [64][256]
        int k = e4 >> 8, r = e4 & 255, u = r >> 2, g = r & 3;
        g_U3p[e4] = U3[k * 256 + g * 64 + u];
        return;
    }
    int e5 = e4 - 16384;
    if (e5 < 98304) {  // WU4p: [192][512]
        int k = e5 >> 9, r = e5 & 511, u = r >> 2, g = r & 3;
        g_WU4p[e5] = (k < 64) ? W4[k * 512 + g * 128 + u]
                              : U4[(k - 64) * 512 + g * 128 + u];
    }
}

// ---------------------------------------------------------------------------
// Phase A: LSTM1 (H=128) + LSTM2 (H=64), 16 samples per CTA.
// hcat rows 0..127 = h1, rows 128..191 = h2; each value duplicated (h,h).
// ---------------------------------------------------------------------------
__global__ void __launch_bounds__(256, 1)
phaseA_kernel(const float* __restrict__ x, const float* __restrict__ W1,
              const float* __restrict__ b1, const float* __restrict__ b2) {
    __shared__ float hcat[192 * HROW];
    __shared__ float xs[T_SEQ * 32];  // duplicated x: [t][2b],[t][2b+1]

    const int tid = threadIdx.x;
    const int b0 = blockIdx.x * BT;

    for (int i = tid; i < T_SEQ * BT; i += 256) {
        int b = i >> 7, t = i & 127;
        float v = x[(b0 + b) * T_SEQ + t];
        xs[t * 32 + 2 * b]     = v;
        xs[t * 32 + 2 * b + 1] = v;
    }
    for (int i = tid; i < 192 * HROW; i += 256) hcat[i] = 0.0f;

    const int u1 = tid & 127, bg1 = tid >> 7;  // 8 samples each
    const int u2 = tid & 63,  bg2 = tid >> 6;  // 4 samples each

    const ulonglong2* __restrict__ U1p2  = (const ulonglong2*)g_U1p;   // [k*128+u1]
    const ulonglong2* __restrict__ WU2p2 = (const ulonglong2*)g_WU2p;  // [k*64 +u2]

    const ull w1if = pack2_(W1[u1], W1[128 + u1]);
    const ull w1go = pack2_(W1[256 + u1], W1[384 + u1]);
    const ull b1if = pack2_(b1[u1], b1[128 + u1]);
    const ull b1go = pack2_(b1[256 + u1], b1[384 + u1]);
    const ull b2if = pack2_(b2[u2], b2[64 + u2]);
    const ull b2go = pack2_(b2[128 + u2], b2[192 + u2]);

    float c1[8], c2[4];
#pragma unroll
    for (int j = 0; j < 8; j++) c1[j] = 0.0f;
#pragma unroll
    for (int j = 0; j < 4; j++) c2[j] = 0.0f;

    __syncthreads();

    for (int t = 0; t < T_SEQ; t++) {
        // ---- layer 1: z1 = x_t*W1 + h1 @ U1 + b1 ----
        ull aif[8], ago[8];
        {
            const float* xp = xs + t * 32 + bg1 * 16;
#pragma unroll
            for (int q = 0; q < 4; q++) {
                ulonglong2 xd = *(const ulonglong2*)(xp + 4 * q);
                aif[2 * q]     = fma2_(xd.x, w1if, b1if);
                ago[2 * q]     = fma2_(xd.x, w1go, b1go);
                aif[2 * q + 1] = fma2_(xd.y, w1if, b1if);
                ago[2 * q + 1] = fma2_(xd.y, w1go, b1go);
            }
        }
        const float* hp = hcat + bg1 * 16;
#pragma unroll 4
        for (int k = 0; k < 128; k++) {
            ulonglong2 w = U1p2[k * 128 + u1];
            ulonglong2 h0 = *(const ulonglong2*)(hp + k * HROW);
            ulonglong2 h1 = *(const ulonglong2*)(hp + k * HROW + 4);
            ulonglong2 h2 = *(const ulonglong2*)(hp + k * HROW + 8);
            ulonglong2 h3 = *(const ulonglong2*)(hp + k * HROW + 12);
            ull hv[8] = {h0.x, h0.y, h1.x, h1.y, h2.x, h2.y, h3.x, h3.y};
#pragma unroll
            for (int j = 0; j < 8; j++) {
                aif[j] = fma2_(hv[j], w.x, aif[j]);
                ago[j] = fma2_(hv[j], w.y, ago[j]);
            }
        }
        __syncthreads();  // all reads of old h1 complete
#pragma unroll
        for (int j = 0; j < 8; j++) {
            float zi, zf, zg, zo;
            unpack2_(aif[j], zi, zf);
            unpack2_(ago[j], zg, zo);
            float iv = sigmoidf_(zi);
            float fv = sigmoidf_(zf);
            float gv = fmaxf(zg, 0.0f);
            float ov = sigmoidf_(zo);
            float c  = fmaf(fv, c1[j], iv * gv);
            c1[j] = c;
            float h = ov * fmaxf(c, 0.0f);
            *(float2*)&hcat[u1 * HROW + bg1 * 16 + 2 * j] = make_float2(h, h);
        }
        __syncthreads();  // new h1 visible

        // ---- layer 2: z2 = h1_t @ W2 + h2 @ U2 + b2 (single K=192 loop) ----
        ull a2if[4], a2go[4];
#pragma unroll
        for (int j = 0; j < 4; j++) { a2if[j] = b2if; a2go[j] = b2go; }
        const float* hp2 = hcat + bg2 * 8;
#pragma unroll 4
        for (int k = 0; k < 192; k++) {
            ulonglong2 w = WU2p2[k * 64 + u2];
            ulonglong2 h0 = *(const ulonglong2*)(hp2 + k * HROW);
            ulonglong2 h1 = *(const ulonglong2*)(hp2 + k * HROW + 4);
            ull hv[4] = {h0.x, h0.y, h1.x, h1.y};
#pragma unroll
            for (int j = 0; j < 4; j++) {
                a2if[j] = fma2_(hv[j], w.x, a2if[j]);
                a2go[j] = fma2_(hv[j], w.y, a2go[j]);
            }
        }
        __syncthreads();  // all reads of old h2 complete
#pragma unroll
        for (int j = 0; j < 4; j++) {
            float zi, zf, zg, zo;
            unpack2_(a2if[j], zi, zf);
            unpack2_(a2go[j], zg, zo);
            float iv = sigmoidf_(zi);
            float fv = sigmoidf_(zf);
            float gv = fmaxf(zg, 0.0f);
            float ov = sigmoidf_(zo);
            float c  = fmaf(fv, c2[j], iv * gv);
            c2[j] = c;
            float h = ov * fmaxf(c, 0.0f);
            *(float2*)&hcat[(128 + u2) * HROW + bg2 * 8 + 2 * j] = make_float2(h, h);
            if (t == T_SEQ - 1) g_h2last[(b0 + bg2 * 4 + j) * 64 + u2] = h;
        }
        // next-iteration layer-1 pass only touches rows <128; the two barriers
        // above separate this write from the next read of rows >=128.
    }
}

// ---------------------------------------------------------------------------
// Phase B: RepeatVector(h2_last) -> LSTM3 (H=64) -> LSTM4 (H=128) -> Dense(1).
// hcat rows 0..63 = h3, rows 64..191 = h4 (duplicated values).
// Layer-3 input path (h2_last @ W3 + b3) is constant over t -> held in regs.
// ---------------------------------------------------------------------------
__global__ void __launch_bounds__(256, 1)
phaseB_kernel(const float* __restrict__ b3, const float* __restrict__ b4,
              const float* __restrict__ Wd, const float* __restrict__ bd,
              float* __restrict__ out) {
    __shared__ float hcat[192 * HROW];
    __shared__ float h2T[64 * 32];  // duplicated: [k][2b],[k][2b+1]

    const int tid = threadIdx.x;
    const int b0 = blockIdx.x * BT;

    for (int i = tid; i < 64 * BT; i += 256) {
        int b = i >> 6, k = i & 63;
        float v = g_h2last[(b0 + b) * 64 + k];
        h2T[k * 32 + 2 * b]     = v;
        h2T[k * 32 + 2 * b + 1] = v;
    }
    for (int i = tid; i < 192 * HROW; i += 256) hcat[i] = 0.0f;

    const int u3 = tid & 63,  bg  = tid >> 6;  // 4 samples
    const int u4 = tid & 127, bg2 = tid >> 7;  // 8 samples
    const int lane16 = tid & 15, bq = tid >> 4;

    const ulonglong2* __restrict__ W3p2  = (const ulonglong2*)g_W3p;
    const ulonglong2* __restrict__ U3p2  = (const ulonglong2*)g_U3p;
    const ulonglong2* __restrict__ WU4p2 = (const ulonglong2*)g_WU4p;

    const ull b4if = pack2_(b4[u4], b4[128 + u4]);
    const ull b4go = pack2_(b4[256 + u4], b4[384 + u4]);
    float wd[8];
#pragma unroll
    for (int r = 0; r < 8; r++) wd[r] = Wd[lane16 + 16 * r];
    const float bdv = bd[0];

    __syncthreads();

    // precompute zx3 = h2_last @ W3 + b3 (constant over t) into registers
    ull zif[4], zgo[4];
    {
        const ull b3if = pack2_(b3[u3], b3[64 + u3]);
        const ull b3go = pack2_(b3[128 + u3], b3[192 + u3]);
#pragma unroll
        for (int j = 0; j < 4; j++) { zif[j] = b3if; zgo[j] = b3go; }
        const float* hpx = h2T + bg * 8;
#pragma unroll 4
        for (int k = 0; k < 64; k++) {
            ulonglong2 w = W3p2[k * 64 + u3];
            ulonglong2 h0 = *(const ulonglong2*)(hpx + k * 32);
            ulonglong2 h1 = *(const ulonglong2*)(hpx + k * 32 + 4);
            ull hv[4] = {h0.x, h0.y, h1.x, h1.y};
#pragma unroll
            for (int j = 0; j < 4; j++) {
                zif[j] = fma2_(hv[j], w.x, zif[j]);
                zgo[j] = fma2_(hv[j], w.y, zgo[j]);
            }
        }
    }

    float c3[4], c4[8];
#pragma unroll
    for (int j = 0; j < 4; j++) c3[j] = 0.0f;
#pragma unroll
    for (int j = 0; j < 8; j++) c4[j] = 0.0f;

    for (int t = 0; t < T_SEQ; t++) {
        // ---- layer 3: z3 = zx3 + h3 @ U3 ----
        ull a3if[4], a3go[4];
#pragma unroll
        for (int j = 0; j < 4; j++) { a3if[j] = zif[j]; a3go[j] = zgo[j]; }
        const float* hp3 = hcat + bg * 8;
#pragma unroll 4
        for (int k = 0; k < 64; k++) {
            ulonglong2 w = U3p2[k * 64 + u3];
            ulonglong2 h0 = *(const ulonglong2*)(hp3 + k * HROW);
            ulonglong2 h1 = *(const ulonglong2*)(hp3 + k * HROW + 4);
            ull hv[4] = {h0.x, h0.y, h1.x, h1.y};
#pragma unroll
            for (int j = 0; j < 4; j++) {
                a3if[j] = fma2_(hv[j], w.x, a3if[j]);
                a3go[j] = fma2_(hv[j], w.y, a3go[j]);
            }
        }
        __syncthreads();
#pragma unroll
        for (int j = 0; j < 4; j++) {
            float zi, zf, zg, zo;
            unpack2_(a3if[j], zi, zf);
            unpack2_(a3go[j], zg, zo);
            float iv = sigmoidf_(zi);
            float fv = sigmoidf_(zf);
            float gv = fmaxf(zg, 0.0f);
            float ov = sigmoidf_(zo);
            float c  = fmaf(fv, c3[j], iv * gv);
            c3[j] = c;
            float h = ov * fmaxf(c, 0.0f);
            *(float2*)&hcat[u3 * HROW + bg * 8 + 2 * j] = make_float2(h, h);
        }
        __syncthreads();

        // ---- layer 4: z4 = h3_t @ W4 + h4 @ U4 + b4 (K=192) ----
        ull a4if[8], a4go[8];
#pragma unroll
        for (int j = 0; j < 8; j++) { a4if[j] = b4if; a4go[j] = b4go; }
        const float* hp4 = hcat + bg2 * 16;
#pragma unroll 4
        for (int k = 0; k < 192; k++) {
            ulonglong2 w = WU4p2[k * 128 + u4];
            ulonglong2 h0 = *(const ulonglong2*)(hp4 + k * HROW);
            ulonglong2 h1 = *(const ulonglong2*)(hp4 + k * HROW + 4);
            ulonglong2 h2 = *(const ulonglong2*)(hp4 + k * HROW + 8);
            ulonglong2 h3 = *(const ulonglong2*)(hp4 + k * HROW + 12);
            ull hv[8] = {h0.x, h0.y, h1.x, h1.y, h2.x, h2.y, h3.x, h3.y};
#pragma unroll
            for (int j = 0; j < 8; j++) {
                a4if[j] = fma2_(hv[j], w.x, a4if[j]);
                a4go[j] = fma2_(hv[j], w.y, a4go[j]);
            }
        }
        __syncthreads();
#pragma unroll
        for (int j = 0; j < 8; j++) {
            float zi, zf, zg, zo;
            unpack2_(a4if[j], zi, zf);
            unpack2_(a4go[j], zg, zo);
            float iv = sigmoidf_(zi);
            float fv = sigmoidf_(zf);
            float gv = fmaxf(zg, 0.0f);
            float ov = sigmoidf_(zo);
            float c  = fmaf(fv, c4[j], iv * gv);
            c4[j] = c;
            float h = ov * fmaxf(c, 0.0f);
            *(float2*)&hcat[(64 + u4) * HROW + bg2 * 16 + 2 * j] = make_float2(h, h);
        }
        __syncthreads();

        // ---- dense: out[b][t] = h4 . Wd + bd (16-lane tree per sample) ----
        float s = 0.0f;
#pragma unroll
        for (int r = 0; r < 8; r++)
            s = fmaf(hcat[(64 + lane16 + 16 * r) * HROW + bq * 2], wd[r], s);
        s += __shfl_xor_sync(0xffffffffu, s, 8);
        s += __shfl_xor_sync(0xffffffffu, s, 4);
        s += __shfl_xor_sync(0xffffffffu, s, 2);
        s += __shfl_xor_sync(0xffffffffu, s, 1);
        if (lane16 == 0) out[(b0 + bq) * T_SEQ + t] = s + bdv;
        // dense reads complete before the first barrier of the next iteration;
        // h4 rows are rewritten only after two more barriers.
    }
}

// ---------------------------------------------------------------------------
extern "C" void kernel_launch(void* const* d_in, const int* in_sizes, int n_in,
                              void* d_out, int out_size) {
    const float* x  = (const float*)d_in[0];
    const float* W1 = (const float*)d_in[1];
    const float* U1 = (const float*)d_in[2];
    const float* b1 = (const float*)d_in[3];
    const float* W2 = (const float*)d_in[4];
    const float* U2 = (const float*)d_in[5];
    const float* b2 = (const float*)d_in[6];
    const float* W3 = (const float*)d_in[7];
    const float* U3 = (const float*)d_in[8];
    const float* b3 = (const float*)d_in[9];
    const float* W4 = (const float*)d_in[10];
    const float* U4 = (const float*)d_in[11];
    const float* b4 = (const float*)d_in[12];
    const float* Wd = (const float*)d_in[13];
    const float* bd = (const float*)d_in[14];
    float* out = (float*)d_out;

    pack_kernel<<<960, 256>>>(U1, W2, U2, W3, U3, W4, U4);
    phaseA_kernel<<<NBLK, 256>>>(x, W1, b1, b2);
    phaseB_kernel<<<NBLK, 256>>>(b3, b4, Wd, bd, out);
}

// round 9
// speedup vs baseline: 1.0006x; 1.0004x over previous
#include <cuda_runtime.h>

// MyModel_83597243450144 : 4-layer LSTM autoencoder, fp32 with packed f32x2 FMA.
// B=2048, T=128, H1=128, H2=64. Gate order i,f,g,o; g uses relu, h = o*relu(c).
//
// Layout tricks (all to feed fma.rn.f32x2 / FFMA2 with zero per-iter packing):
//  - weights packed [k][u][i,f,g,o] -> one LDG.128 = two f32x2 regs (w_if, w_go)
//  - hidden state / x duplicated in shared (h,h) -> one LDS.128 = two dup f32x2
//  - accumulators pair gates: a_if = (z_i,z_f), a_go = (z_g,z_o)

#define B_ALL 2048
#define T_SEQ 128
#define BT 16
#define NBLK (B_ALL / BT)  // 128 CTAs
#define HROW 36            // shared row stride in floats (32 dup data + 4 pad), 16B-mult

typedef unsigned long long ull;

// ---- device scratch (no allocations allowed) ----
__device__ float g_U1p[128 * 512];   // [k][u*4+g]  (U1 repacked)
__device__ float g_WU2p[192 * 256];  // k<128: W2, k>=128: U2
__device__ float g_W3p[64 * 256];
__device__ float g_U3p[64 * 256];
__device__ float g_WU4p[192 * 512];  // k<64: W4, k>=64: U4
__device__ float g_h2last[B_ALL * 64];

__device__ __forceinline__ float sigmoidf_(float v) {
    return __fdividef(1.0f, 1.0f + __expf(-v));
}
__device__ __forceinline__ ull pack2_(float lo, float hi) {
    ull r;
    asm("mov.b64 %0, {%1, %2};" : "=l"(r) : "f"(lo), "f"(hi));
    return r;
}
__device__ __forceinline__ void unpack2_(ull v, float& lo, float& hi) {
    asm("mov.b64 {%0, %1}, %2;" : "=f"(lo), "=f"(hi) : "l"(v));
}
__device__ __forceinline__ ull fma2_(ull a, ull b, ull c) {
    ull d;
    asm("fma.rn.f32x2 %0, %1, %2, %3;" : "=l"(d) : "l"(a), "l"(b), "l"(c));
    return d;
}

// ---------------------------------------------------------------------------
// Weight repack: per hidden unit u, the 4 gate weights (i,f,g,o) contiguous.
// Total elements = 65536 + 49152 + 16384 + 16384 + 98304 = 245760 = 960*256.
// ---------------------------------------------------------------------------
__global__ void pack_kernel(const float* __restrict__ U1,
                            const float* __restrict__ W2, const float* __restrict__ U2,
                            const float* __restrict__ W3, const float* __restrict__ U3,
                            const float* __restrict__ W4, const float* __restrict__ U4) {
    int e = blockIdx.x * blockDim.x + threadIdx.x;
    if (e < 65536) {  // U1p: [128][512]
        int k = e >> 9, r = e & 511, u = r >> 2, g = r & 3;
        g_U1p[e] = U1[k * 512 + g * 128 + u];
        return;
    }
    int e2 = e - 65536;
    if (e2 < 49152) {  // WU2p: [192][256]
        int k = e2 >> 8, r = e2 & 255, u = r >> 2, g = r & 3;
        g_WU2p[e2] = (k < 128) ? W2[k * 256 + g * 64 + u]
                               : U2[(k - 128) * 256 + g * 64 + u];
        return;
    }
    int e3 = e2 - 49152;
    if (e3 < 16384) {  // W3p: [64][256]
        int k = e3 >> 8, r = e3 & 255, u = r >> 2, g = r & 3;
        g_W3p[e3] = W3[k * 256 + g * 64 + u];
        return;
    }
    int e4 = e3 - 16384;
    if (e4 < 16384) {  // U3p: [64][256]
        int k = e4 >> 8, r = e4 & 255, u = r >> 2, g = r & 3;
        g_U3p[e4] = U3[k * 256 + g * 64 + u];
        return;
    }
    int e5 = e4 - 16384;
    if (e5 < 98304) {  // WU4p: [192][512]
        int k = e5 >> 9, r = e5 & 511, u = r >> 2, g = r & 3;
        g_WU4p[e5] = (k < 64) ? W4[k * 512 + g * 128 + u]
                              : U4[(k - 64) * 512 + g * 128 + u];
    }
}

// ---------------------------------------------------------------------------
// Phase A: LSTM1 (H=128) + LSTM2 (H=64), 16 samples per CTA.
// hcat rows 0..127 = h1, rows 128..191 = h2; each value duplicated (h,h).
// ---------------------------------------------------------------------------
__global__ void __launch_bounds__(256, 1)
phaseA_kernel(const float* __restrict__ x, const float* __restrict__ W1,
              const float* __restrict__ b1, const float* __restrict__ b2) {
    __shared__ float hcat[192 * HROW];
    __shared__ float xs[T_SEQ * 32];  // duplicated x: [t][2b],[t][2b+1]

    const int tid = threadIdx.x;
    const int b0 = blockIdx.x * BT;

    for (int i = tid; i < T_SEQ * BT; i += 256) {
        int b = i >> 7, t = i & 127;
        float v = x[(b0 + b) * T_SEQ + t];
        xs[t * 32 + 2 * b]     = v;
        xs[t * 32 + 2 * b + 1] = v;
    }
    for (int i = tid; i < 192 * HROW; i += 256) hcat[i] = 0.0f;

    const int u1 = tid & 127, bg1 = tid >> 7;  // 8 samples each
    const int u2 = tid & 63,  bg2 = tid >> 6;  // 4 samples each

    const ulonglong2* __restrict__ U1p2  = (const ulonglong2*)g_U1p;   // [k*128+u1]
    const ulonglong2* __restrict__ WU2p2 = (const ulonglong2*)g_WU2p;  // [k*64 +u2]

    const ull w1if = pack2_(W1[u1], W1[128 + u1]);
    const ull w1go = pack2_(W1[256 + u1], W1[384 + u1]);
    const ull b1if = pack2_(b1[u1], b1[128 + u1]);
    const ull b1go = pack2_(b1[256 + u1], b1[384 + u1]);
    const ull b2if = pack2_(b2[u2], b2[64 + u2]);
    const ull b2go = pack2_(b2[128 + u2], b2[192 + u2]);

    float c1[8], c2[4];
#pragma unroll
    for (int j = 0; j < 8; j++) c1[j] = 0.0f;
#pragma unroll
    for (int j = 0; j < 4; j++) c2[j] = 0.0f;

    __syncthreads();

    for (int t = 0; t < T_SEQ; t++) {
        // ---- layer 1: z1 = x_t*W1 + h1 @ U1 + b1 ----
        ull aif[8], ago[8];
        {
            const float* xp = xs + t * 32 + bg1 * 16;
#pragma unroll
            for (int q = 0; q < 4; q++) {
                ulonglong2 xd = *(const ulonglong2*)(xp + 4 * q);
                aif[2 * q]     = fma2_(xd.x, w1if, b1if);
                ago[2 * q]     = fma2_(xd.x, w1go, b1go);
                aif[2 * q + 1] = fma2_(xd.y, w1if, b1if);
                ago[2 * q + 1] = fma2_(xd.y, w1go, b1go);
            }
        }
        const float* hp = hcat + bg1 * 16;
#pragma unroll 4
        for (int k = 0; k < 128; k++) {
            ulonglong2 w = U1p2[k * 128 + u1];
            ulonglong2 h0 = *(const ulonglong2*)(hp + k * HROW);
            ulonglong2 h1 = *(const ulonglong2*)(hp + k * HROW + 4);
            ulonglong2 h2 = *(const ulonglong2*)(hp + k * HROW + 8);
            ulonglong2 h3 = *(const ulonglong2*)(hp + k * HROW + 12);
            ull hv[8] = {h0.x, h0.y, h1.x, h1.y, h2.x, h2.y, h3.x, h3.y};
#pragma unroll
            for (int j = 0; j < 8; j++) {
                aif[j] = fma2_(hv[j], w.x, aif[j]);
                ago[j] = fma2_(hv[j], w.y, ago[j]);
            }
        }
        __syncthreads();  // all reads of old h1 complete
#pragma unroll
        for (int j = 0; j < 8; j++) {
            float zi, zf, zg, zo;
            unpack2_(aif[j], zi, zf);
            unpack2_(ago[j], zg, zo);
            float iv = sigmoidf_(zi);
            float fv = sigmoidf_(zf);
            float gv = fmaxf(zg, 0.0f);
            float ov = sigmoidf_(zo);
            float c  = fmaf(fv, c1[j], iv * gv);
            c1[j] = c;
            float h = ov * fmaxf(c, 0.0f);
            *(float2*)&hcat[u1 * HROW + bg1 * 16 + 2 * j] = make_float2(h, h);
        }
        __syncthreads();  // new h1 visible

        // ---- layer 2: z2 = h1_t @ W2 + h2 @ U2 + b2 (single K=192 loop) ----
        ull a2if[4], a2go[4];
#pragma unroll
        for (int j = 0; j < 4; j++) { a2if[j] = b2if; a2go[j] = b2go; }
        const float* hp2 = hcat + bg2 * 8;
#pragma unroll 4
        for (int k = 0; k < 192; k++) {
            ulonglong2 w = WU2p2[k * 64 + u2];
            ulonglong2 h0 = *(const ulonglong2*)(hp2 + k * HROW);
            ulonglong2 h1 = *(const ulonglong2*)(hp2 + k * HROW + 4);
            ull hv[4] = {h0.x, h0.y, h1.x, h1.y};
#pragma unroll
            for (int j = 0; j < 4; j++) {
                a2if[j] = fma2_(hv[j], w.x, a2if[j]);
                a2go[j] = fma2_(hv[j], w.y, a2go[j]);
            }
        }
        __syncthreads();  // all reads of old h2 complete
#pragma unroll
        for (int j = 0; j < 4; j++) {
            float zi, zf, zg, zo;
            unpack2_(a2if[j], zi, zf);
            unpack2_(a2go[j], zg, zo);
            float iv = sigmoidf_(zi);
            float fv = sigmoidf_(zf);
            float gv = fmaxf(zg, 0.0f);
            float ov = sigmoidf_(zo);
            float c  = fmaf(fv, c2[j], iv * gv);
            c2[j] = c;
            float h = ov * fmaxf(c, 0.0f);
            *(float2*)&hcat[(128 + u2) * HROW + bg2 * 8 + 2 * j] = make_float2(h, h);
            if (t == T_SEQ - 1) g_h2last[(b0 + bg2 * 4 + j) * 64 + u2] = h;
        }
        // next-iteration layer-1 pass only touches rows <128; the two barriers
        // above separate this write from the next read of rows >=128.
    }
}

// ---------------------------------------------------------------------------
// Phase B: RepeatVector(h2_last) -> LSTM3 (H=64) -> LSTM4 (H=128) -> Dense(1).
// hcat rows 0..63 = h3, rows 64..191 = h4 (duplicated values).
// Layer-3 input path (h2_last @ W3 + b3) is constant over t -> held in regs.
// ---------------------------------------------------------------------------
__global__ void __launch_bounds__(256, 1)
phaseB_kernel(const float* __restrict__ b3, const float* __restrict__ b4,
              const float* __restrict__ Wd, const float* __restrict__ bd,
              float* __restrict__ out) {
    __shared__ float hcat[192 * HROW];
    __shared__ float h2T[64 * 32];  // duplicated: [k][2b],[k][2b+1]

    const int tid = threadIdx.x;
    const int b0 = blockIdx.x * BT;

    for (int i = tid; i < 64 * BT; i += 256) {
        int b = i >> 6, k = i & 63;
        float v = g_h2last[(b0 + b) * 64 + k];
        h2T[k * 32 + 2 * b]     = v;
        h2T[k * 32 + 2 * b + 1] = v;
    }
    for (int i = tid; i < 192 * HROW; i += 256) hcat[i] = 0.0f;

    const int u3 = tid & 63,  bg  = tid >> 6;  // 4 samples
    const int u4 = tid & 127, bg2 = tid >> 7;  // 8 samples
    const int lane16 = tid & 15, bq = tid >> 4;

    const ulonglong2* __restrict__ W3p2  = (const ulonglong2*)g_W3p;
    const ulonglong2* __restrict__ U3p2  = (const ulonglong2*)g_U3p;
    const ulonglong2* __restrict__ WU4p2 = (const ulonglong2*)g_WU4p;

    const ull b4if = pack2_(b4[u4], b4[128 + u4]);
    const ull b4go = pack2_(b4[256 + u4], b4[384 + u4]);
    float wd[8];
#pragma unroll
    for (int r = 0; r < 8; r++) wd[r] = Wd[lane16 + 16 * r];
    const float bdv = bd[0];

    __syncthreads();

    // precompute zx3 = h2_last @ W3 + b3 (constant over t) into registers
    ull zif[4], zgo[4];
    {
        const ull b3if = pack2_(b3[u3], b3[64 + u3]);
        const ull b3go = pack2_(b3[128 + u3], b3[192 + u3]);
#pragma unroll
        for (int j = 0; j < 4; j++) { zif[j] = b3if; zgo[j] = b3go; }
        const float* hpx = h2T + bg * 8;
#pragma unroll 4
        for (int k = 0; k < 64; k++) {
            ulonglong2 w = W3p2[k * 64 + u3];
            ulonglong2 h0 = *(const ulonglong2*)(hpx + k * 32);
            ulonglong2 h1 = *(const ulonglong2*)(hpx + k * 32 + 4);
            ull hv[4] = {h0.x, h0.y, h1.x, h1.y};
#pragma unroll
            for (int j = 0; j < 4; j++) {
                zif[j] = fma2_(hv[j], w.x, zif[j]);
                zgo[j] = fma2_(hv[j], w.y, zgo[j]);
            }
        }
    }

    float c3[4], c4[8];
#pragma unroll
    for (int j = 0; j < 4; j++) c3[j] = 0.0f;
#pragma unroll
    for (int j = 0; j < 8; j++) c4[j] = 0.0f;

    for (int t = 0; t < T_SEQ; t++) {
        // ---- layer 3: z3 = zx3 + h3 @ U3 ----
        ull a3if[4], a3go[4];
#pragma unroll
        for (int j = 0; j < 4; j++) { a3if[j] = zif[j]; a3go[j] = zgo[j]; }
        const float* hp3 = hcat + bg * 8;
#pragma unroll 4
        for (int k = 0; k < 64; k++) {
            ulonglong2 w = U3p2[k * 64 + u3];
            ulonglong2 h0 = *(const ulonglong2*)(hp3 + k * HROW);
            ulonglong2 h1 = *(const ulonglong2*)(hp3 + k * HROW + 4);
            ull hv[4] = {h0.x, h0.y, h1.x, h1.y};
#pragma unroll
            for (int j = 0; j < 4; j++) {
                a3if[j] = fma2_(hv[j], w.x, a3if[j]);
                a3go[j] = fma2_(hv[j], w.y, a3go[j]);
            }
        }
        __syncthreads();
#pragma unroll
        for (int j = 0; j < 4; j++) {
            float zi, zf, zg, zo;
            unpack2_(a3if[j], zi, zf);
            unpack2_(a3go[j], zg, zo);
            float iv = sigmoidf_(zi);
            float fv = sigmoidf_(zf);
            float gv = fmaxf(zg, 0.0f);
            float ov = sigmoidf_(zo);
            float c  = fmaf(fv, c3[j], iv * gv);
            c3[j] = c;
            float h = ov * fmaxf(c, 0.0f);
            *(float2*)&hcat[u3 * HROW + bg * 8 + 2 * j] = make_float2(h, h);
        }
        __syncthreads();

        // ---- layer 4: z4 = h3_t @ W4 + h4 @ U4 + b4 (K=192) ----
        ull a4if[8], a4go[8];
#pragma unroll
        for (int j = 0; j < 8; j++) { a4if[j] = b4if; a4go[j] = b4go; }
        const float* hp4 = hcat + bg2 * 16;
#pragma unroll 4
        for (int k = 0; k < 192; k++) {
            ulonglong2 w = WU4p2[k * 128 + u4];
            ulonglong2 h0 = *(const ulonglong2*)(hp4 + k * HROW);
            ulonglong2 h1 = *(const ulonglong2*)(hp4 + k * HROW + 4);
            ulonglong2 h2 = *(const ulonglong2*)(hp4 + k * HROW + 8);
            ulonglong2 h3 = *(const ulonglong2*)(hp4 + k * HROW + 12);
            ull hv[8] = {h0.x, h0.y, h1.x, h1.y, h2.x, h2.y, h3.x, h3.y};
#pragma unroll
            for (int j = 0; j < 8; j++) {
                a4if[j] = fma2_(hv[j], w.x, a4if[j]);
                a4go[j] = fma2_(hv[j], w.y, a4go[j]);
            }
        }
        __syncthreads();
#pragma unroll
        for (int j = 0; j < 8; j++) {
            float zi, zf, zg, zo;
            unpack2_(a4if[j], zi, zf);
            unpack2_(a4go[j], zg, zo);
            float iv = sigmoidf_(zi);
            float fv = sigmoidf_(zf);
            float gv = fmaxf(zg, 0.0f);
            float ov = sigmoidf_(zo);
            float c  = fmaf(fv, c4[j], iv * gv);
            c4[j] = c;
            float h = ov * fmaxf(c, 0.0f);
            *(float2*)&hcat[(64 + u4) * HROW + bg2 * 16 + 2 * j] = make_float2(h, h);
        }
        __syncthreads();

        // ---- dense: out[b][t] = h4 . Wd + bd (16-lane tree per sample) ----
        float s = 0.0f;
#pragma unroll
        for (int r = 0; r < 8; r++)
            s = fmaf(hcat[(64 + lane16 + 16 * r) * HROW + bq * 2], wd[r], s);
        s += __shfl_xor_sync(0xffffffffu, s, 8);
        s += __shfl_xor_sync(0xffffffffu, s, 4);
        s += __shfl_xor_sync(0xffffffffu, s, 2);
        s += __shfl_xor_sync(0xffffffffu, s, 1);
        if (lane16 == 0) out[(b0 + bq) * T_SEQ + t] = s + bdv;
        // dense reads complete before the first barrier of the next iteration;
        // h4 rows are rewritten only after two more barriers.
    }
}

// ---------------------------------------------------------------------------
extern "C" void kernel_launch(void* const* d_in, const int* in_sizes, int n_in,
                              void* d_out, int out_size) {
    const float* x  = (const float*)d_in[0];
    const float* W1 = (const float*)d_in[1];
    const float* U1 = (const float*)d_in[2];
    const float* b1 = (const float*)d_in[3];
    const float* W2 = (const float*)d_in[4];
    const float* U2 = (const float*)d_in[5];
    const float* b2 = (const float*)d_in[6];
    const float* W3 = (const float*)d_in[7];
    const float* U3 = (const float*)d_in[8];
    const float* b3 = (const float*)d_in[9];
    const float* W4 = (const float*)d_in[10];
    const float* U4 = (const float*)d_in[11];
    const float* b4 = (const float*)d_in[12];
    const float* Wd = (const float*)d_in[13];
    const float* bd = (const float*)d_in[14];
    float* out = (float*)d_out;

    pack_kernel<<<960, 256>>>(U1, W2, U2, W3, U3, W4, U4);
    phaseA_kernel<<<NBLK, 256>>>(x, W1, b1, b2);
    phaseB_kernel<<<NBLK, 256>>>(b3, b4, Wd, bd, out);
}

// round 10
// speedup vs baseline: 1.5305x; 1.5296x over previous
#include <cuda_runtime.h>

// MyModel_83597243450144 : 4-layer LSTM autoencoder, fp32 + packed f32x2 FMA.
// B=2048, T=128, H1=128, H2=64. Gate order i,f,g,o; g relu, h = o*relu(c).
//
// This round: 512 threads/CTA with K-split halves (A: low k, B: high k) to
// double warps/SMSP and halve each warp's serial L2-latency LDG chain.
// Partials combined via shared [slot][ltid] buffer (conflict-free 64-bit).
// Sigmoid via single-MUFU tanh.approx.

#define B_ALL 2048
#define T_SEQ 128
#define BT 16
#define NBLK (B_ALL / BT)  // 128 CTAs
#define HROW 36            // hcat row stride (floats): 32 dup data + 4 pad

typedef unsigned long long ull;

// ---- device scratch (no allocations allowed) ----
__device__ float g_U1p[128 * 512];   // [k][u*4+g]
__device__ float g_WU2p[192 * 256];  // k<128: W2, k>=128: U2
__device__ float g_W3p[64 * 256];
__device__ float g_U3p[64 * 256];
__device__ float g_WU4p[192 * 512];  // k<64: W4, k>=64: U4
__device__ float g_h2last[B_ALL * 64];

__device__ __forceinline__ float sigmoidf_(float v) {
    float t, h = 0.5f * v;
    asm("tanh.approx.f32 %0, %1;" : "=f"(t) : "f"(h));
    return fmaf(0.5f, t, 0.5f);
}
__device__ __forceinline__ ull pack2_(float lo, float hi) {
    ull r;
    asm("mov.b64 %0, {%1, %2};" : "=l"(r) : "f"(lo), "f"(hi));
    return r;
}
__device__ __forceinline__ void unpack2_(ull v, float& lo, float& hi) {
    asm("mov.b64 {%0, %1}, %2;" : "=f"(lo), "=f"(hi) : "l"(v));
}
__device__ __forceinline__ ull fma2_(ull a, ull b, ull c) {
    ull d;
    asm("fma.rn.f32x2 %0, %1, %2, %3;" : "=l"(d) : "l"(a), "l"(b), "l"(c));
    return d;
}
__device__ __forceinline__ ull add2_(ull a, ull b) {
    ull d;
    asm("add.rn.f32x2 %0, %1, %2;" : "=l"(d) : "l"(a), "l"(b));
    return d;
}

// ---------------------------------------------------------------------------
// Weight repack: per unit u, 4 gate weights (i,f,g,o) contiguous -> LDG.128.
// Total = 65536+49152+16384+16384+98304 = 245760 = 960*256.
// ---------------------------------------------------------------------------
__global__ void pack_kernel(const float* __restrict__ U1,
                            const float* __restrict__ W2, const float* __restrict__ U2,
                            const float* __restrict__ W3, const float* __restrict__ U3,
                            const float* __restrict__ W4, const float* __restrict__ U4) {
    int e = blockIdx.x * blockDim.x + threadIdx.x;
    if (e < 65536) {
        int k = e >> 9, r = e & 511, u = r >> 2, g = r & 3;
        g_U1p[e] = U1[k * 512 + g * 128 + u];
        return;
    }
    int e2 = e - 65536;
    if (e2 < 49152) {
        int k = e2 >> 8, r = e2 & 255, u = r >> 2, g = r & 3;
        g_WU2p[e2] = (k < 128) ? W2[k * 256 + g * 64 + u]
                               : U2[(k - 128) * 256 + g * 64 + u];
        return;
    }
    int e3 = e2 - 49152;
    if (e3 < 16384) {
        int k = e3 >> 8, r = e3 & 255, u = r >> 2, g = r & 3;
        g_W3p[e3] = W3[k * 256 + g * 64 + u];
        return;
    }
    int e4 = e3 - 16384;
    if (e4 < 16384) {
        int k = e4 >> 8, r = e4 & 255, u = r >> 2, g = r & 3;
        g_U3p[e4] = U3[k * 256 + g * 64 + u];
        return;
    }
    int e5 = e4 - 16384;
    if (e5 < 98304) {
        int k = e5 >> 9, r = e5 & 511, u = r >> 2, g = r & 3;
        g_WU4p[e5] = (k < 64) ? W4[k * 512 + g * 128 + u]
                              : U4[(k - 64) * 512 + g * 128 + u];
    }
}

// ---------------------------------------------------------------------------
// Phase A: LSTM1 (H=128) + LSTM2 (H=64), 16 samples per CTA, 512 threads.
// hcat rows 0..127 = h1, 128..191 = h2, values duplicated (h,h).
// Half A (tid<256): k-low + bias/x path + reduce + epilogue; half B: k-high.
// ---------------------------------------------------------------------------
#define SMEMA_BYTES (((192 * HROW) + (T_SEQ * 32)) * 4 + 16 * 256 * 8)  // 76800
#define SMEMB_BYTES (((192 * HROW) + (64 * 32)) * 4 + 16 * 256 * 8)     // 68608

__global__ void __launch_bounds__(512, 1)
phaseA_kernel(const float* __restrict__ x, const float* __restrict__ W1,
              const float* __restrict__ b1, const float* __restrict__ b2) {
    extern __shared__ float smem[];
    float* hcat = smem;                         // 192*HROW floats
    float* xs   = smem + 192 * HROW;            // 128*32 floats (dup x)
    ull*   pbuf = (ull*)(smem + 192 * HROW + T_SEQ * 32);  // [16][256]

    const int tid = threadIdx.x;
    const int half = tid >> 8, ltid = tid & 255;
    const int b0 = blockIdx.x * BT;

    for (int i = tid; i < T_SEQ * BT; i += 512) {
        int b = i >> 7, t = i & 127;
        float v = x[(b0 + b) * T_SEQ + t];
        xs[t * 32 + 2 * b]     = v;
        xs[t * 32 + 2 * b + 1] = v;
    }
    for (int i = tid; i < 192 * HROW; i += 512) hcat[i] = 0.0f;

    const int u1 = ltid & 127, bg1 = ltid >> 7;  // 8 samples per (u1,bg1)
    const int u2 = ltid & 63,  bg2 = ltid >> 6;  // 4 samples per (u2,bg2)

    const ulonglong2* __restrict__ U1p2  = (const ulonglong2*)g_U1p;
    const ulonglong2* __restrict__ WU2p2 = (const ulonglong2*)g_WU2p;

    const ull w1if = pack2_(W1[u1], W1[128 + u1]);
    const ull w1go = pack2_(W1[256 + u1], W1[384 + u1]);
    const ull b1if = pack2_(b1[u1], b1[128 + u1]);
    const ull b1go = pack2_(b1[256 + u1], b1[384 + u1]);
    const ull b2if = pack2_(b2[u2], b2[64 + u2]);
    const ull b2go = pack2_(b2[128 + u2], b2[192 + u2]);

    float c1[8], c2[4];
#pragma unroll
    for (int j = 0; j < 8; j++) c1[j] = 0.0f;
#pragma unroll
    for (int j = 0; j < 4; j++) c2[j] = 0.0f;

    __syncthreads();

    for (int t = 0; t < T_SEQ; t++) {
        // ================= layer 1 : z1 = x*W1 + h1@U1 + b1 =================
        ull aif[8], ago[8];
        if (half == 0) {
            const ulonglong2* xp = (const ulonglong2*)(xs + t * 32 + bg1 * 16);
#pragma unroll
            for (int q = 0; q < 4; q++) {
                ulonglong2 xd = xp[q];
                aif[2 * q]     = fma2_(xd.x, w1if, b1if);
                ago[2 * q]     = fma2_(xd.x, w1go, b1go);
                aif[2 * q + 1] = fma2_(xd.y, w1if, b1if);
                ago[2 * q + 1] = fma2_(xd.y, w1go, b1go);
            }
        } else {
#pragma unroll
            for (int j = 0; j < 8; j++) { aif[j] = 0ull; ago[j] = 0ull; }
        }
        {
            const int kbase = half << 6;  // 0 or 64
            const float* hp = hcat + kbase * HROW + bg1 * 16;
            const ulonglong2* wrow = U1p2 + (size_t)kbase * 128 + u1;
#pragma unroll 4
            for (int kk = 0; kk < 64; kk++) {
                ulonglong2 w = wrow[kk * 128];
                const ulonglong2* hq = (const ulonglong2*)(hp + kk * HROW);
                ulonglong2 hA = hq[0];
                aif[0] = fma2_(hA.x, w.x, aif[0]); ago[0] = fma2_(hA.x, w.y, ago[0]);
                aif[1] = fma2_(hA.y, w.x, aif[1]); ago[1] = fma2_(hA.y, w.y, ago[1]);
                ulonglong2 hB = hq[1];
                aif[2] = fma2_(hB.x, w.x, aif[2]); ago[2] = fma2_(hB.x, w.y, ago[2]);
                aif[3] = fma2_(hB.y, w.x, aif[3]); ago[3] = fma2_(hB.y, w.y, ago[3]);
                ulonglong2 hC = hq[2];
                aif[4] = fma2_(hC.x, w.x, aif[4]); ago[4] = fma2_(hC.x, w.y, ago[4]);
                aif[5] = fma2_(hC.y, w.x, aif[5]); ago[5] = fma2_(hC.y, w.y, ago[5]);
                ulonglong2 hD = hq[3];
                aif[6] = fma2_(hD.x, w.x, aif[6]); ago[6] = fma2_(hD.x, w.y, ago[6]);
                aif[7] = fma2_(hD.y, w.x, aif[7]); ago[7] = fma2_(hD.y, w.y, ago[7]);
            }
        }
        if (half == 1) {
#pragma unroll
            for (int j = 0; j < 8; j++) {
                pbuf[(2 * j) * 256 + ltid]     = aif[j];
                pbuf[(2 * j + 1) * 256 + ltid] = ago[j];
            }
        }
        __syncthreads();  // partials visible; all reads of old h1 complete
        if (half == 0) {
#pragma unroll
            for (int j = 0; j < 8; j++) {
                ull zif = add2_(aif[j], pbuf[(2 * j) * 256 + ltid]);
                ull zgo = add2_(ago[j], pbuf[(2 * j + 1) * 256 + ltid]);
                float zi, zf, zg, zo;
                unpack2_(zif, zi, zf);
                unpack2_(zgo, zg, zo);
                float iv = sigmoidf_(zi), fv = sigmoidf_(zf);
                float gv = fmaxf(zg, 0.0f), ov = sigmoidf_(zo);
                float c = fmaf(fv, c1[j], iv * gv);
                c1[j] = c;
                float h = ov * fmaxf(c, 0.0f);
                *(float2*)&hcat[u1 * HROW + bg1 * 16 + 2 * j] = make_float2(h, h);
            }
        }
        __syncthreads();  // new h1 visible

        // ======= layer 2 : z2 = h1@W2 + h2@U2 + b2  (K=192, split 96/96) =====
        ull a2if[4], a2go[4];
        if (half == 0) {
#pragma unroll
            for (int j = 0; j < 4; j++) { a2if[j] = b2if; a2go[j] = b2go; }
        } else {
#pragma unroll
            for (int j = 0; j < 4; j++) { a2if[j] = 0ull; a2go[j] = 0ull; }
        }
        {
            const int kbase = half * 96;
            const float* hp2 = hcat + kbase * HROW + bg2 * 8;
            const ulonglong2* wrow = WU2p2 + (size_t)kbase * 64 + u2;
#pragma unroll 4
            for (int kk = 0; kk < 96; kk++) {
                ulonglong2 w = wrow[kk * 64];
                const ulonglong2* hq = (const ulonglong2*)(hp2 + kk * HROW);
                ulonglong2 hA = hq[0];
                a2if[0] = fma2_(hA.x, w.x, a2if[0]); a2go[0] = fma2_(hA.x, w.y, a2go[0]);
                a2if[1] = fma2_(hA.y, w.x, a2if[1]); a2go[1] = fma2_(hA.y, w.y, a2go[1]);
                ulonglong2 hB = hq[1];
                a2if[2] = fma2_(hB.x, w.x, a2if[2]); a2go[2] = fma2_(hB.x, w.y, a2go[2]);
                a2if[3] = fma2_(hB.y, w.x, a2if[3]); a2go[3] = fma2_(hB.y, w.y, a2go[3]);
            }
        }
        if (half == 1) {
#pragma unroll
            for (int j = 0; j < 4; j++) {
                pbuf[(2 * j) * 256 + ltid]     = a2if[j];
                pbuf[(2 * j + 1) * 256 + ltid] = a2go[j];
            }
        }
        __syncthreads();  // partials visible; all reads of old h2 complete
        if (half == 0) {
#pragma unroll
            for (int j = 0; j < 4; j++) {
                ull zif = add2_(a2if[j], pbuf[(2 * j) * 256 + ltid]);
                ull zgo = add2_(a2go[j], pbuf[(2 * j + 1) * 256 + ltid]);
                float zi, zf, zg, zo;
                unpack2_(zif, zi, zf);
                unpack2_(zgo, zg, zo);
                float iv = sigmoidf_(zi), fv = sigmoidf_(zf);
                float gv = fmaxf(zg, 0.0f), ov = sigmoidf_(zo);
                float c = fmaf(fv, c2[j], iv * gv);
                c2[j] = c;
                float h = ov * fmaxf(c, 0.0f);
                *(float2*)&hcat[(128 + u2) * HROW + bg2 * 8 + 2 * j] = make_float2(h, h);
                if (t == T_SEQ - 1) g_h2last[(b0 + bg2 * 4 + j) * 64 + u2] = h;
            }
        }
        __syncthreads();  // new h2 visible
    }
}

// ---------------------------------------------------------------------------
// Phase B: RepeatVector(h2_last) -> LSTM3 (64) -> LSTM4 (128) -> Dense(1).
// hcat rows 0..63 = h3, rows 64..191 = h4 (dup). Layer-3 input path constant
// over t -> precomputed once in half-A registers. 512 threads, K-split halves.
// ---------------------------------------------------------------------------
__global__ void __launch_bounds__(512, 1)
phaseB_kernel(const float* __restrict__ b3, const float* __restrict__ b4,
              const float* __restrict__ Wd, const float* __restrict__ bd,
              float* __restrict__ out) {
    extern __shared__ float smem[];
    float* hcat = smem;                     // 192*HROW
    float* h2T  = smem + 192 * HROW;        // 64*32 (dup)
    ull*   pbuf = (ull*)(smem + 192 * HROW + 64 * 32);  // [16][256]

    const int tid = threadIdx.x;
    const int half = tid >> 8, ltid = tid & 255;
    const int b0 = blockIdx.x * BT;

    for (int i = tid; i < 64 * BT; i += 512) {
        int b = i >> 6, k = i & 63;
        float v = g_h2last[(b0 + b) * 64 + k];
        h2T[k * 32 + 2 * b]     = v;
        h2T[k * 32 + 2 * b + 1] = v;
    }
    for (int i = tid; i < 192 * HROW; i += 512) hcat[i] = 0.0f;

    const int u3 = ltid & 63,  bg  = ltid >> 6;  // 4 samples
    const int u4 = ltid & 127, bg2 = ltid >> 7;  // 8 samples
    const int lane16 = tid & 15, bq = (tid >> 4) & 15;

    const ulonglong2* __restrict__ W3p2  = (const ulonglong2*)g_W3p;
    const ulonglong2* __restrict__ U3p2  = (const ulonglong2*)g_U3p;
    const ulonglong2* __restrict__ WU4p2 = (const ulonglong2*)g_WU4p;

    const ull b4if = pack2_(b4[u4], b4[128 + u4]);
    const ull b4go = pack2_(b4[256 + u4], b4[384 + u4]);
    float wd[8];
    if (tid < 256) {
#pragma unroll
        for (int r = 0; r < 8; r++) wd[r] = Wd[lane16 + 16 * r];
    }
    const float bdv = bd[0];

    __syncthreads();

    // zx3 = h2_last @ W3 + b3 (constant over t), half-A registers only
    ull zif[4], zgo[4];
    if (half == 0) {
        const ull b3if = pack2_(b3[u3], b3[64 + u3]);
        const ull b3go = pack2_(b3[128 + u3], b3[192 + u3]);
#pragma unroll
        for (int j = 0; j < 4; j++) { zif[j] = b3if; zgo[j] = b3go; }
        const float* hpx = h2T + bg * 8;
#pragma unroll 4
        for (int k = 0; k < 64; k++) {
            ulonglong2 w = W3p2[k * 64 + u3];
            const ulonglong2* hq = (const ulonglong2*)(hpx + k * 32);
            ulonglong2 hA = hq[0], hB = hq[1];
            zif[0] = fma2_(hA.x, w.x, zif[0]); zgo[0] = fma2_(hA.x, w.y, zgo[0]);
            zif[1] = fma2_(hA.y, w.x, zif[1]); zgo[1] = fma2_(hA.y, w.y, zgo[1]);
            zif[2] = fma2_(hB.x, w.x, zif[2]); zgo[2] = fma2_(hB.x, w.y, zgo[2]);
            zif[3] = fma2_(hB.y, w.x, zif[3]); zgo[3] = fma2_(hB.y, w.y, zgo[3]);
        }
    }

    float c3[4], c4[8];
#pragma unroll
    for (int j = 0; j < 4; j++) c3[j] = 0.0f;
#pragma unroll
    for (int j = 0; j < 8; j++) c4[j] = 0.0f;

    for (int t = 0; t < T_SEQ; t++) {
        // ================= layer 3 : z3 = zx3 + h3@U3 (K=64, 32/32) ==========
        ull a3if[4], a3go[4];
        if (half == 0) {
#pragma unroll
            for (int j = 0; j < 4; j++) { a3if[j] = zif[j]; a3go[j] = zgo[j]; }
        } else {
#pragma unroll
            for (int j = 0; j < 4; j++) { a3if[j] = 0ull; a3go[j] = 0ull; }
        }
        {
            const int kbase = half << 5;  // 0 or 32
            const float* hp3 = hcat + kbase * HROW + bg * 8;
            const ulonglong2* wrow = U3p2 + (size_t)kbase * 64 + u3;
#pragma unroll 4
            for (int kk = 0; kk < 32; kk++) {
                ulonglong2 w = wrow[kk * 64];
                const ulonglong2* hq = (const ulonglong2*)(hp3 + kk * HROW);
                ulonglong2 hA = hq[0], hB = hq[1];
                a3if[0] = fma2_(hA.x, w.x, a3if[0]); a3go[0] = fma2_(hA.x, w.y, a3go[0]);
                a3if[1] = fma2_(hA.y, w.x, a3if[1]); a3go[1] = fma2_(hA.y, w.y, a3go[1]);
                a3if[2] = fma2_(hB.x, w.x, a3if[2]); a3go[2] = fma2_(hB.x, w.y, a3go[2]);
                a3if[3] = fma2_(hB.y, w.x, a3if[3]); a3go[3] = fma2_(hB.y, w.y, a3go[3]);
            }
        }
        if (half == 1) {
#pragma unroll
            for (int j = 0; j < 4; j++) {
                pbuf[(2 * j) * 256 + ltid]     = a3if[j];
                pbuf[(2 * j + 1) * 256 + ltid] = a3go[j];
            }
        }
        __syncthreads();
        if (half == 0) {
#pragma unroll
            for (int j = 0; j < 4; j++) {
                ull zf2 = add2_(a3if[j], pbuf[(2 * j) * 256 + ltid]);
                ull zg2 = add2_(a3go[j], pbuf[(2 * j + 1) * 256 + ltid]);
                float zi, zf, zg, zo;
                unpack2_(zf2, zi, zf);
                unpack2_(zg2, zg, zo);
                float iv = sigmoidf_(zi), fv = sigmoidf_(zf);
                float gv = fmaxf(zg, 0.0f), ov = sigmoidf_(zo);
                float c = fmaf(fv, c3[j], iv * gv);
                c3[j] = c;
                float h = ov * fmaxf(c, 0.0f);
                *(float2*)&hcat[u3 * HROW + bg * 8 + 2 * j] = make_float2(h, h);
            }
        }
        __syncthreads();

        // ========== layer 4 : z4 = h3@W4 + h4@U4 + b4 (K=192, 96/96) =========
        ull a4if[8], a4go[8];
        if (half == 0) {
#pragma unroll
            for (int j = 0; j < 8; j++) { a4if[j] = b4if; a4go[j] = b4go; }
        } else {
#pragma unroll
            for (int j = 0; j < 8; j++) { a4if[j] = 0ull; a4go[j] = 0ull; }
        }
        {
            const int kbase = half * 96;
            const float* hp4 = hcat + kbase * HROW + bg2 * 16;
            const ulonglong2* wrow = WU4p2 + (size_t)kbase * 128 + u4;
#pragma unroll 4
            for (int kk = 0; kk < 96; kk++) {
                ulonglong2 w = wrow[kk * 128];
                const ulonglong2* hq = (const ulonglong2*)(hp4 + kk * HROW);
                ulonglong2 hA = hq[0];
                a4if[0] = fma2_(hA.x, w.x, a4if[0]); a4go[0] = fma2_(hA.x, w.y, a4go[0]);
                a4if[1] = fma2_(hA.y, w.x, a4if[1]); a4go[1] = fma2_(hA.y, w.y, a4go[1]);
                ulonglong2 hB = hq[1];
                a4if[2] = fma2_(hB.x, w.x, a4if[2]); a4go[2] = fma2_(hB.x, w.y, a4go[2]);
                a4if[3] = fma2_(hB.y, w.x, a4if[3]); a4go[3] = fma2_(hB.y, w.y, a4go[3]);
                ulonglong2 hC = hq[2];
                a4if[4] = fma2_(hC.x, w.x, a4if[4]); a4go[4] = fma2_(hC.x, w.y, a4go[4]);
                a4if[5] = fma2_(hC.y, w.x, a4if[5]); a4go[5] = fma2_(hC.y, w.y, a4go[5]);
                ulonglong2 hD = hq[3];
                a4if[6] = fma2_(hD.x, w.x, a4if[6]); a4go[6] = fma2_(hD.x, w.y, a4go[6]);
                a4if[7] = fma2_(hD.y, w.x, a4if[7]); a4go[7] = fma2_(hD.y, w.y, a4go[7]);
            }
        }
        if (half == 1) {
#pragma unroll
            for (int j = 0; j < 8; j++) {
                pbuf[(2 * j) * 256 + ltid]     = a4if[j];
                pbuf[(2 * j + 1) * 256 + ltid] = a4go[j];
            }
        }
        __syncthreads();
        if (half == 0) {
#pragma unroll
            for (int j = 0; j < 8; j++) {
                ull zf2 = add2_(a4if[j], pbuf[(2 * j) * 256 + ltid]);
                ull zg2 = add2_(a4go[j], pbuf[(2 * j + 1) * 256 + ltid]);
                float zi, zf, zg, zo;
                unpack2_(zf2, zi, zf);
                unpack2_(zg2, zg, zo);
                float iv = sigmoidf_(zi), fv = sigmoidf_(zf);
                float gv = fmaxf(zg, 0.0f), ov = sigmoidf_(zo);
                float c = fmaf(fv, c4[j], iv * gv);
                c4[j] = c;
                float h = ov * fmaxf(c, 0.0f);
                *(float2*)&hcat[(64 + u4) * HROW + bg2 * 16 + 2 * j] = make_float2(h, h);
            }
        }
        __syncthreads();  // h4(t) visible

        // ---- dense: out[b][t] = h4 . Wd + bd (16 lanes per sample) ----
        if (tid < 256) {
            float s = 0.0f;
#pragma unroll
            for (int r = 0; r < 8; r++)
                s = fmaf(hcat[(64 + lane16 + 16 * r) * HROW + bq * 2], wd[r], s);
            s += __shfl_xor_sync(0xffffffffu, s, 8);
            s += __shfl_xor_sync(0xffffffffu, s, 4);
            s += __shfl_xor_sync(0xffffffffu, s, 2);
            s += __shfl_xor_sync(0xffffffffu, s, 1);
            if (lane16 == 0) out[(b0 + bq) * T_SEQ + t] = s + bdv;
        }
        // dense reads finish before this thread's next bar; h4 rows rewritten
        // only after the next step's layer-4 partial barrier.
    }
}

// ---------------------------------------------------------------------------
extern "C" void kernel_launch(void* const* d_in, const int* in_sizes, int n_in,
                              void* d_out, int out_size) {
    const float* x  = (const float*)d_in[0];
    const float* W1 = (const float*)d_in[1];
    const float* U1 = (const float*)d_in[2];
    const float* b1 = (const float*)d_in[3];
    const float* W2 = (const float*)d_in[4];
    const float* U2 = (const float*)d_in[5];
    const float* b2 = (const float*)d_in[6];
    const float* W3 = (const float*)d_in[7];
    const float* U3 = (const float*)d_in[8];
    const float* b3 = (const float*)d_in[9];
    const float* W4 = (const float*)d_in[10];
    const float* U4 = (const float*)d_in[11];
    const float* b4 = (const float*)d_in[12];
    const float* Wd = (const float*)d_in[13];
    const float* bd = (const float*)d_in[14];
    float* out = (float*)d_out;

    static int attr_done = 0;
    if (!attr_done) {
        cudaFuncSetAttribute(phaseA_kernel,
                             cudaFuncAttributeMaxDynamicSharedMemorySize, SMEMA_BYTES);
        cudaFuncSetAttribute(phaseB_kernel,
                             cudaFuncAttributeMaxDynamicSharedMemorySize, SMEMB_BYTES);
        attr_done = 1;
    }

    pack_kernel<<<960, 256>>>(U1, W2, U2, W3, U3, W4, U4);
    phaseA_kernel<<<NBLK, 512, SMEMA_BYTES>>>(x, W1, b1, b2);
    phaseB_kernel<<<NBLK, 512, SMEMB_BYTES>>>(b3, b4, Wd, bd, out);
}

// round 13
// speedup vs baseline: 2.8117x; 1.8372x over previous
#include <cuda_runtime.h>
#include <cuda_fp16.h>

// MyModel_83597243450144 : 4-layer LSTM autoencoder, tensor-core split-fp16.
// B=2048, T=128, H1=128, H2=64. Gates i,f,g,o; g relu, h = o*relu(c).
// z = hi@Whi + hi@Wlo + lo@Whi via mma.sync.m16n8k16 (f16 in, f32 acc).

#define B_ALL 2048
#define T_SEQ 128
#define BT 16
#define NBLK (B_ALL / BT)
#define RS1 136  // h row stride (halves) for H=128 buffers (128+8)
#define RS2 72   // for H=64 buffers (64+8)

typedef unsigned int uint;

// ---- device scratch ----
__device__ uint4 g_wfrag[57344];  // fragment-packed split weights
__device__ float g_h2last[B_ALL * 64];

#define SEC_L1 0
#define SEC_L2 16384
#define SEC_L3 28672
#define SEC_L4 32768

__device__ __forceinline__ float sigmoidf_(float v) {
    float r, h = 0.5f * v;
    asm("tanh.approx.f32 %0, %1;" : "=f"(r) : "f"(h));
    return fmaf(0.5f, r, 0.5f);
}
__device__ __forceinline__ uint packh_(__half lo, __half hi) {
    return (uint)__half_as_ushort(lo) | ((uint)__half_as_ushort(hi) << 16);
}
__device__ __forceinline__ uint ldh2_(const __half* p) {
    return *(const uint*)p;
}
__device__ __forceinline__ void mma16816(float* c, uint a0, uint a1, uint a2,
                                         uint a3, uint b0, uint b1) {
    asm("mma.sync.aligned.m16n8k16.row.col.f32.f16.f16.f32 "
        "{%0,%1,%2,%3}, {%4,%5,%6,%7}, {%8,%9}, {%0,%1,%2,%3};"
        : "+f"(c[0]), "+f"(c[1]), "+f"(c[2]), "+f"(c[3])
        : "r"(a0), "r"(a1), "r"(a2), "r"(a3), "r"(b0), "r"(b1));
}
__device__ __forceinline__ float lstm_cell(float zi, float zf, float zg,
                                           float zo, float& c) {
    float iv = sigmoidf_(zi), fv = sigmoidf_(zf);
    float gv = fmaxf(zg, 0.0f), ov = sigmoidf_(zo);
    c = fmaf(fv, c, iv * gv);
    return ov * fmaxf(c, 0.0f);
}
__device__ __forceinline__ void split_store(__half* bhi, __half* blo, int idx,
                                            float h) {
    __half hh = __float2half_rn(h);
    bhi[idx] = hh;
    blo[idx] = __float2half_rn(h - __half2float(hh));
}

// GEMM partial over NKB k-blocks starting at kb0. C[gate*NBG + j2][4].
// A from (bhi,blo) smem, row stride rs halves. Weight section wsec, whose
// layout is uint4[(nb*KBTOT + kb)*32 + lane] = {b0hi,b1hi,b0lo,b1lo}.
template <int NKB, int KBTOT, int NBG>
__device__ __forceinline__ void gemm_part(float (*C)[4], const uint4* wsec,
                                          int kb0, const __half* bhi,
                                          const __half* blo, int rs,
                                          int w, int g, int t) {
    const uint4* wl = wsec + (threadIdx.x & 31);
#pragma unroll
    for (int kk = 0; kk < NKB; kk++) {
        const int kb = kb0 + kk;
        const int c0 = kk * 16 + 2 * t;
        uint a0 = ldh2_(bhi + g * rs + c0);
        uint a1 = ldh2_(bhi + (g + 8) * rs + c0);
        uint a2 = ldh2_(bhi + g * rs + c0 + 8);
        uint a3 = ldh2_(bhi + (g + 8) * rs + c0 + 8);
        uint l0 = ldh2_(blo + g * rs + c0);
        uint l1 = ldh2_(blo + (g + 8) * rs + c0);
        uint l2 = ldh2_(blo + g * rs + c0 + 8);
        uint l3 = ldh2_(blo + (g + 8) * rs + c0 + 8);
#pragma unroll
        for (int gg = 0; gg < 4; gg++)
#pragma unroll
            for (int j2 = 0; j2 < NBG; j2++) {
                int nb = gg * (NBG * 8) + (NBG == 2 ? 2 * w + j2 : w);
                uint4 wf = wl[(nb * KBTOT + kb) * 32];
                float* c = C[gg * NBG + j2];
                mma16816(c, a0, a1, a2, a3, wf.x, wf.y);  // hi*Whi
                mma16816(c, a0, a1, a2, a3, wf.z, wf.w);  // hi*Wlo
                mma16816(c, l0, l1, l2, l3, wf.x, wf.y);  // lo*Whi
            }
    }
}

// ---------------------------------------------------------------------------
// Pack weights into split B-fragment layout.
// b0 rows {2t,2t+1}, b1 rows {2t+8,2t+9}; col n = nb*8 + g (gate-major).
// ---------------------------------------------------------------------------
__global__ void pack_kernel(const float* __restrict__ U1,
                            const float* __restrict__ W2, const float* __restrict__ U2,
                            const float* __restrict__ U3,
                            const float* __restrict__ W4, const float* __restrict__ U4) {
    int e = blockIdx.x * 256 + threadIdx.x;
    if (e >= 57344) return;
    int sec, KB, idx;
    if (e < 16384)      { sec = 0; KB = 8;  idx = e; }
    else if (e < 28672) { sec = 1; KB = 12; idx = e - 16384; }
    else if (e < 32768) { sec = 2; KB = 4;  idx = e - 28672; }
    else                { sec = 3; KB = 12; idx = e - 32768; }
    int lane = idx & 31, rest = idx >> 5;
    int kb = rest % KB, nb = rest / KB;
    int g = lane >> 2, t = lane & 3;
    int n = nb * 8 + g;
    __half h[4], l[4];
#pragma unroll
    for (int r = 0; r < 4; r++) {
        int k = kb * 16 + 2 * t + (r & 1) + (r >> 1) * 8;
        float v;
        if (sec == 0)      v = U1[k * 512 + n];
        else if (sec == 1) v = (k < 128) ? W2[k * 256 + n] : U2[(k - 128) * 256 + n];
        else if (sec == 2) v = U3[k * 256 + n];
        else               v = (k < 64) ? W4[k * 512 + n] : U4[(k - 64) * 512 + n];
        h[r] = __float2half_rn(v);
        l[r] = __float2half_rn(v - __half2float(h[r]));
    }
    uint4 o;
    o.x = packh_(h[0], h[1]);
    o.y = packh_(h[2], h[3]);
    o.z = packh_(l[0], l[1]);
    o.w = packh_(l[2], l[3]);
    g_wfrag[e] = o;
}

// ---------------------------------------------------------------------------
// Phase A: LSTM1 (H=128) + LSTM2 (H=64). 256 threads, 16 samples/CTA.
// ---------------------------------------------------------------------------
__global__ void __launch_bounds__(256, 1)
phaseA_kernel(const float* __restrict__ x, const float* __restrict__ W1,
              const float* __restrict__ b1, const float* __restrict__ b2) {
    __shared__ __half h1hi[16 * RS1], h1lo[16 * RS1];
    __shared__ __half h2hi[16 * RS2], h2lo[16 * RS2];
    __shared__ float xs[16 * 132];

    const int tid = threadIdx.x;
    const int w = tid >> 5, lane = tid & 31, g = lane >> 2, t = lane & 3;
    const int b0 = blockIdx.x * BT;

    for (int i = tid; i < BT * T_SEQ; i += 256) {
        int b = i >> 7, s = i & 127;
        xs[b * 132 + s] = x[(b0 + b) * T_SEQ + s];
    }
    for (int i = tid; i < 16 * RS1; i += 256) { h1hi[i] = __ushort_as_half(0); h1lo[i] = __ushort_as_half(0); }
    for (int i = tid; i < 16 * RS2; i += 256) { h2hi[i] = __ushort_as_half(0); h2lo[i] = __ushort_as_half(0); }

    const int u1 = 16 * w + 2 * t;  // layer-1/4 unit base
    const int u2 = 8 * w + 2 * t;   // layer-2/3 unit base

    float b1v[16], w1v[16], b2v[8];
#pragma unroll
    for (int gg = 0; gg < 4; gg++)
#pragma unroll
        for (int j2 = 0; j2 < 2; j2++)
#pragma unroll
            for (int e1 = 0; e1 < 2; e1++) {
                int col = gg * 128 + u1 + j2 * 8 + e1;
                b1v[gg * 4 + j2 * 2 + e1] = b1[col];
                w1v[gg * 4 + j2 * 2 + e1] = W1[col];
            }
#pragma unroll
    for (int gg = 0; gg < 4; gg++)
#pragma unroll
        for (int e1 = 0; e1 < 2; e1++)
            b2v[gg * 2 + e1] = b2[gg * 64 + u2 + e1];

    float c1[8], c2[4];
#pragma unroll
    for (int j = 0; j < 8; j++) c1[j] = 0.0f;
#pragma unroll
    for (int j = 0; j < 4; j++) c2[j] = 0.0f;

    __syncthreads();

    for (int tt = 0; tt < T_SEQ; tt++) {
        // ---- layer 1: z1 = x*W1 + h1@U1 + b1 ----
        float C1[8][4];
        {
            float xv0 = xs[g * 132 + tt], xv1 = xs[(g + 8) * 132 + tt];
#pragma unroll
            for (int gg = 0; gg < 4; gg++)
#pragma unroll
                for (int j2 = 0; j2 < 2; j2++)
#pragma unroll
                    for (int e = 0; e < 4; e++) {
                        int idx = gg * 4 + j2 * 2 + (e & 1);
                        C1[gg * 2 + j2][e] = fmaf((e & 2) ? xv1 : xv0, w1v[idx], b1v[idx]);
                    }
        }
        gemm_part<8, 8, 2>(C1, g_wfrag + SEC_L1, 0, h1hi, h1lo, RS1, w, g, t);
        __syncthreads();  // all h1(t-1) reads done
#pragma unroll
        for (int j2 = 0; j2 < 2; j2++)
#pragma unroll
            for (int e = 0; e < 4; e++) {
                int u = u1 + j2 * 8 + (e & 1);
                int s = g + ((e & 2) ? 8 : 0);
                float h = lstm_cell(C1[0 + j2][e], C1[2 + j2][e], C1[4 + j2][e],
                                    C1[6 + j2][e], c1[j2 * 4 + e]);
                split_store(h1hi, h1lo, s * RS1 + u, h);
            }
        __syncthreads();  // h1(t) visible

        // ---- layer 2: z2 = h1@W2 + h2@U2 + b2 (K=192) ----
        float C2[4][4];
#pragma unroll
        for (int gg = 0; gg < 4; gg++)
#pragma unroll
            for (int e = 0; e < 4; e++) C2[gg][e] = b2v[gg * 2 + (e & 1)];
        gemm_part<8, 12, 1>(C2, g_wfrag + SEC_L2, 0, h1hi, h1lo, RS1, w, g, t);
        gemm_part<4, 12, 1>(C2, g_wfrag + SEC_L2, 8, h2hi, h2lo, RS2, w, g, t);
        __syncthreads();  // all h2(t-1) reads done
#pragma unroll
        for (int e = 0; e < 4; e++) {
            int u = u2 + (e & 1);
            int s = g + ((e & 2) ? 8 : 0);
            float h = lstm_cell(C2[0][e], C2[1][e], C2[2][e], C2[3][e], c2[e]);
            split_store(h2hi, h2lo, s * RS2 + u, h);
            if (tt == T_SEQ - 1) g_h2last[(b0 + s) * 64 + u] = h;
        }
        // h2(t) writes vs next-step L2 reads: separated by next step's 2 bars
    }
}

// ---------------------------------------------------------------------------
// Phase B: Repeat(h2last) -> LSTM3 (64) -> LSTM4 (128) -> Dense(1).
// zx3 = h2last@W3 + b3 precomputed per thread in fp32 (constant over t).
// ---------------------------------------------------------------------------
__global__ void __launch_bounds__(256, 1)
phaseB_kernel(const float* __restrict__ W3, const float* __restrict__ b3,
              const float* __restrict__ b4, const float* __restrict__ Wd,
              const float* __restrict__ bd, float* __restrict__ out) {
    __shared__ __half h3hi[16 * RS2], h3lo[16 * RS2];
    __shared__ __half h4hi[16 * RS1], h4lo[16 * RS1];
    __shared__ float h2s[16 * 66];
    __shared__ float pd[128];

    const int tid = threadIdx.x;
    const int w = tid >> 5, lane = tid & 31, g = lane >> 2, t = lane & 3;
    const int b0 = blockIdx.x * BT;

    for (int i = tid; i < BT * 64; i += 256) {
        int b = i >> 6, k = i & 63;
        h2s[b * 66 + k] = g_h2last[(b0 + b) * 64 + k];
    }
    for (int i = tid; i < 16 * RS2; i += 256) { h3hi[i] = __ushort_as_half(0); h3lo[i] = __ushort_as_half(0); }
    for (int i = tid; i < 16 * RS1; i += 256) { h4hi[i] = __ushort_as_half(0); h4lo[i] = __ushort_as_half(0); }

    const int u1 = 16 * w + 2 * t;
    const int u2 = 8 * w + 2 * t;

    float b4v[16], wd[4];
#pragma unroll
    for (int gg = 0; gg < 4; gg++)
#pragma unroll
        for (int j2 = 0; j2 < 2; j2++)
#pragma unroll
            for (int e1 = 0; e1 < 2; e1++)
                b4v[gg * 4 + j2 * 2 + e1] = b4[gg * 128 + u1 + j2 * 8 + e1];
    wd[0] = Wd[u1]; wd[1] = Wd[u1 + 1]; wd[2] = Wd[u1 + 8]; wd[3] = Wd[u1 + 9];
    const float bdv = bd[0];

    __syncthreads();

    // zx3[gg][e] = b3 + h2last @ W3 (fp32 exact, constant over t)
    float zx[4][4];
#pragma unroll
    for (int gg = 0; gg < 4; gg++)
#pragma unroll
        for (int e = 0; e < 4; e++) zx[gg][e] = b3[gg * 64 + u2 + (e & 1)];
    for (int k = 0; k < 64; k++) {
        float ha = h2s[g * 66 + k], hb = h2s[(g + 8) * 66 + k];
#pragma unroll
        for (int gg = 0; gg < 4; gg++) {
            float w0 = W3[k * 256 + gg * 64 + u2];
            float w1 = W3[k * 256 + gg * 64 + u2 + 1];
            zx[gg][0] = fmaf(ha, w0, zx[gg][0]);
            zx[gg][1] = fmaf(ha, w1, zx[gg][1]);
            zx[gg][2] = fmaf(hb, w0, zx[gg][2]);
            zx[gg][3] = fmaf(hb, w1, zx[gg][3]);
        }
    }

    float c3[4], c4[8];
#pragma unroll
    for (int j = 0; j < 4; j++) c3[j] = 0.0f;
#pragma unroll
    for (int j = 0; j < 8; j++) c4[j] = 0.0f;

    for (int tt = 0; tt < T_SEQ; tt++) {
        // ---- layer 3: z3 = zx3 + h3@U3 (K=64) ----
        float C3[4][4];
#pragma unroll
        for (int gg = 0; gg < 4; gg++)
#pragma unroll
            for (int e = 0; e < 4; e++) C3[gg][e] = zx[gg][e];
        gemm_part<4, 4, 1>(C3, g_wfrag + SEC_L3, 0, h3hi, h3lo, RS2, w, g, t);
        __syncthreads();  // h3(t-1) reads done
#pragma unroll
        for (int e = 0; e < 4; e++) {
            int u = u2 + (e & 1);
            int s = g + ((e & 2) ? 8 : 0);
            float h = lstm_cell(C3[0][e], C3[1][e], C3[2][e], C3[3][e], c3[e]);
            split_store(h3hi, h3lo, s * RS2 + u, h);
        }
        __syncthreads();  // h3(t) visible

        // ---- layer 4: z4 = h3@W4 + h4@U4 + b4 (K=192) ----
        float C4[8][4];
#pragma unroll
        for (int gg = 0; gg < 4; gg++)
#pragma unroll
            for (int j2 = 0; j2 < 2; j2++)
#pragma unroll
                for (int e = 0; e < 4; e++)
                    C4[gg * 2 + j2][e] = b4v[gg * 4 + j2 * 2 + (e & 1)];
        gemm_part<4, 12, 2>(C4, g_wfrag + SEC_L4, 0, h3hi, h3lo, RS2, w, g, t);
        gemm_part<8, 12, 2>(C4, g_wfrag + SEC_L4, 4, h4hi, h4lo, RS1, w, g, t);
        __syncthreads();  // h4(t-1) + h3(t) reads done
        float pA = 0.0f, pB = 0.0f;
#pragma unroll
        for (int j2 = 0; j2 < 2; j2++)
#pragma unroll
            for (int e = 0; e < 4; e++) {
                int u = u1 + j2 * 8 + (e & 1);
                int s = g + ((e & 2) ? 8 : 0);
                float h = lstm_cell(C4[0 + j2][e], C4[2 + j2][e], C4[4 + j2][e],
                                    C4[6 + j2][e], c4[j2 * 4 + e]);
                split_store(h4hi, h4lo, s * RS1 + u, h);
                float wv = wd[j2 * 2 + (e & 1)];
                if (e & 2) pB = fmaf(h, wv, pB);
                else       pA = fmaf(h, wv, pA);
            }
        // reduce dense partials over the 4 t-lanes of each g-group
        pA += __shfl_xor_sync(0xffffffffu, pA, 1);
        pA += __shfl_xor_sync(0xffffffffu, pA, 2);
        pB += __shfl_xor_sync(0xffffffffu, pB, 1);
        pB += __shfl_xor_sync(0xffffffffu, pB, 2);
        if (t == 0) {
            pd[w * 16 + g] = pA;
            pd[w * 16 + 8 + g] = pB;
        }
        __syncthreads();  // h4(t) + pd visible
        if (tid < 16) {
            float s_ = bdv;
#pragma unroll
            for (int wi = 0; wi < 8; wi++) s_ += pd[wi * 16 + tid];
            out[(b0 + tid) * T_SEQ + tt] = s_;
        }
        // pd rewritten only after next step's 3rd barrier -> safe
    }
}

// ---------------------------------------------------------------------------
extern "C" void kernel_launch(void* const* d_in, const int* in_sizes, int n_in,
                              void* d_out, int out_size) {
    const float* x  = (const float*)d_in[0];
    const float* W1 = (const float*)d_in[1];
    const float* U1 = (const float*)d_in[2];
    const float* b1 = (const float*)d_in[3];
    const float* W2 = (const float*)d_in[4];
    const float* U2 = (const float*)d_in[5];
    const float* b2 = (const float*)d_in[6];
    const float* W3 = (const float*)d_in[7];
    const float* U3 = (const float*)d_in[8];
    const float* b3 = (const float*)d_in[9];
    const float* W4 = (const float*)d_in[10];
    const float* U4 = (const float*)d_in[11];
    const float* b4 = (const float*)d_in[12];
    const float* Wd = (const float*)d_in[13];
    const float* bd = (const float*)d_in[14];
    float* out = (float*)d_out;

    pack_kernel<<<224, 256>>>(U1, W2, U2, U3, W4, U4);
    phaseA_kernel<<<NBLK, 256>>>(x, W1, b1, b2);
    phaseB_kernel<<<NBLK, 256>>>(W3, b3, b4, Wd, bd, out);
}

// round 14
// speedup vs baseline: 4.6660x; 1.6595x over previous
#include <cuda_runtime.h>
#include <cuda_fp16.h>

// MyModel_83597243450144 : 4-layer LSTM autoencoder, tensor-core split-fp16.
// B=2048, T=128, H1=128, H2=64. Gates i,f,g,o; g relu, h = o*relu(c).
// z = hi@Whi + hi@Wlo + lo@Whi via mma.sync.m16n8k16 (f16 in, f32 acc).
// R14: 512 threads / 16 warps; N-split for the H=128 layers, K-split + smem
// reduction for the H=64 layers -> per-warp mma/LDG chains halved.

#define B_ALL 2048
#define T_SEQ 128
#define BT 16
#define NBLK (B_ALL / BT)
#define RS1 136  // h row stride (halves) for H=128 buffers (128+8)
#define RS2 72   // for H=64 buffers (64+8)

typedef unsigned int uint;

// ---- device scratch ----
__device__ uint4 g_wfrag[57344];  // fragment-packed split weights
__device__ float g_h2last[B_ALL * 64];

#define SEC_L1 0
#define SEC_L2 16384
#define SEC_L3 28672
#define SEC_L4 32768

__device__ __forceinline__ float sigmoidf_(float v) {
    float r, h = 0.5f * v;
    asm("tanh.approx.f32 %0, %1;" : "=f"(r) : "f"(h));
    return fmaf(0.5f, r, 0.5f);
}
__device__ __forceinline__ uint packh_(__half lo, __half hi) {
    return (uint)__half_as_ushort(lo) | ((uint)__half_as_ushort(hi) << 16);
}
__device__ __forceinline__ uint ldh2_(const __half* p) {
    return *(const uint*)p;
}
__device__ __forceinline__ void mma16816(float* c, uint a0, uint a1, uint a2,
                                         uint a3, uint b0, uint b1) {
    asm("mma.sync.aligned.m16n8k16.row.col.f32.f16.f16.f32 "
        "{%0,%1,%2,%3}, {%4,%5,%6,%7}, {%8,%9}, {%0,%1,%2,%3};"
        : "+f"(c[0]), "+f"(c[1]), "+f"(c[2]), "+f"(c[3])
        : "r"(a0), "r"(a1), "r"(a2), "r"(a3), "r"(b0), "r"(b1));
}
__device__ __forceinline__ float lstm_cell(float zi, float zf, float zg,
                                           float zo, float& c) {
    float iv = sigmoidf_(zi), fv = sigmoidf_(zf);
    float gv = fmaxf(zg, 0.0f), ov = sigmoidf_(zo);
    c = fmaf(fv, c, iv * gv);
    return ov * fmaxf(c, 0.0f);
}
__device__ __forceinline__ void split_store(__half* bhi, __half* blo, int idx,
                                            float h) {
    __half hh = __float2half_rn(h);
    bhi[idx] = hh;
    blo[idx] = __float2half_rn(h - __half2float(hh));
}

// GEMM partial: NKB k-blocks, weights at kb0..kb0+NKB-1 of a KBTOT-block
// section; A read from column 0 of (bhi,blo). nb = gg*nb_gs + nb_w.
// C[gg][4]: c0,c1 = sample g cols {2t,2t+1}; c2,c3 = sample g+8.
template <int NKB, int KBTOT>
__device__ __forceinline__ void gemm_part(float (*C)[4], const uint4* wsec,
                                          int kb0, int nb_w, int nb_gs,
                                          const __half* bhi, const __half* blo,
                                          int rs, int g, int t) {
    const uint4* wl = wsec + (threadIdx.x & 31);
#pragma unroll
    for (int kk = 0; kk < NKB; kk++) {
        const int kb = kb0 + kk;
        const int c0 = kk * 16 + 2 * t;
        uint a0 = ldh2_(bhi + g * rs + c0);
        uint a1 = ldh2_(bhi + (g + 8) * rs + c0);
        uint a2 = ldh2_(bhi + g * rs + c0 + 8);
        uint a3 = ldh2_(bhi + (g + 8) * rs + c0 + 8);
        uint l0 = ldh2_(blo + g * rs + c0);
        uint l1 = ldh2_(blo + (g + 8) * rs + c0);
        uint l2 = ldh2_(blo + g * rs + c0 + 8);
        uint l3 = ldh2_(blo + (g + 8) * rs + c0 + 8);
#pragma unroll
        for (int gg = 0; gg < 4; gg++) {
            int nb = gg * nb_gs + nb_w;
            uint4 wf = wl[(nb * KBTOT + kb) * 32];
            float* c = C[gg];
            mma16816(c, a0, a1, a2, a3, wf.x, wf.y);  // hi*Whi
            mma16816(c, a0, a1, a2, a3, wf.z, wf.w);  // hi*Wlo
            mma16816(c, l0, l1, l2, l3, wf.x, wf.y);  // lo*Whi
        }
    }
}

// ---------------------------------------------------------------------------
// Pack weights into split B-fragment layout (layout identical to R13).
// ---------------------------------------------------------------------------
__global__ void pack_kernel(const float* __restrict__ U1,
                            const float* __restrict__ W2, const float* __restrict__ U2,
                            const float* __restrict__ U3,
                            const float* __restrict__ W4, const float* __restrict__ U4) {
    int e = blockIdx.x * 256 + threadIdx.x;
    if (e >= 57344) return;
    int sec, KB, idx;
    if (e < 16384)      { sec = 0; KB = 8;  idx = e; }
    else if (e < 28672) { sec = 1; KB = 12; idx = e - 16384; }
    else if (e < 32768) { sec = 2; KB = 4;  idx = e - 28672; }
    else                { sec = 3; KB = 12; idx = e - 32768; }
    int lane = idx & 31, rest = idx >> 5;
    int kb = rest % KB, nb = rest / KB;
    int g = lane >> 2, t = lane & 3;
    int n = nb * 8 + g;
    __half h[4], l[4];
#pragma unroll
    for (int r = 0; r < 4; r++) {
        int k = kb * 16 + 2 * t + (r & 1) + (r >> 1) * 8;
        float v;
        if (sec == 0)      v = U1[k * 512 + n];
        else if (sec == 1) v = (k < 128) ? W2[k * 256 + n] : U2[(k - 128) * 256 + n];
        else if (sec == 2) v = U3[k * 256 + n];
        else               v = (k < 64) ? W4[k * 512 + n] : U4[(k - 64) * 512 + n];
        h[r] = __float2half_rn(v);
        l[r] = __float2half_rn(v - __half2float(h[r]));
    }
    uint4 o;
    o.x = packh_(h[0], h[1]);
    o.y = packh_(h[2], h[3]);
    o.z = packh_(l[0], l[1]);
    o.w = packh_(l[2], l[3]);
    g_wfrag[e] = o;
}

// ---------------------------------------------------------------------------
// Phase A: LSTM1 (H=128) + LSTM2 (H=64). 512 threads, 16 samples/CTA.
// L1: full K per warp, nb = gg*16 + w. L2: K split 96/96 by w>>3, nb =
// gg*8 + (w&7); partials via pbuf; epilogue on warps 0-7.
// ---------------------------------------------------------------------------
__global__ void __launch_bounds__(512, 1)
phaseA_kernel(const float* __restrict__ x, const float* __restrict__ W1,
              const float* __restrict__ b1, const float* __restrict__ b2) {
    __shared__ __half h1hi[16 * RS1], h1lo[16 * RS1];
    __shared__ __half h2hi[16 * RS2], h2lo[16 * RS2];
    __shared__ float xs[16 * 132];
    __shared__ float pbuf[16][256];

    const int tid = threadIdx.x;
    const int w = tid >> 5, lane = tid & 31, g = lane >> 2, t = lane & 3;
    const int wl = w & 7, kh = w >> 3;
    const int b0 = blockIdx.x * BT;

    for (int i = tid; i < BT * T_SEQ; i += 512) {
        int b = i >> 7, s = i & 127;
        xs[b * 132 + s] = x[(b0 + b) * T_SEQ + s];
    }
    for (int i = tid; i < 16 * RS1; i += 512) { h1hi[i] = __ushort_as_half(0); h1lo[i] = __ushort_as_half(0); }
    for (int i = tid; i < 16 * RS2; i += 512) { h2hi[i] = __ushort_as_half(0); h2lo[i] = __ushort_as_half(0); }

    const int u1 = 8 * w + 2 * t;    // layer-1 unit base (16 warps)
    const int u2 = 8 * wl + 2 * t;   // layer-2 unit base (warp halves)

    float b1v[8], w1v[8], b2v[8];
#pragma unroll
    for (int gg = 0; gg < 4; gg++)
#pragma unroll
        for (int e1 = 0; e1 < 2; e1++) {
            int col = gg * 128 + u1 + e1;
            b1v[gg * 2 + e1] = b1[col];
            w1v[gg * 2 + e1] = W1[col];
            b2v[gg * 2 + e1] = b2[gg * 64 + u2 + e1];
        }

    float c1[4], c2[4];
#pragma unroll
    for (int j = 0; j < 4; j++) { c1[j] = 0.0f; c2[j] = 0.0f; }

    __syncthreads();

    for (int tt = 0; tt < T_SEQ; tt++) {
        // ---- layer 1: z1 = x*W1 + h1@U1 + b1 (full K per warp) ----
        float C1[4][4];
        {
            float xv0 = xs[g * 132 + tt], xv1 = xs[(g + 8) * 132 + tt];
#pragma unroll
            for (int gg = 0; gg < 4; gg++)
#pragma unroll
                for (int e = 0; e < 4; e++) {
                    int idx = gg * 2 + (e & 1);
                    C1[gg][e] = fmaf((e & 2) ? xv1 : xv0, w1v[idx], b1v[idx]);
                }
        }
        gemm_part<8, 8>(C1, g_wfrag + SEC_L1, 0, w, 16, h1hi, h1lo, RS1, g, t);
        __syncthreads();  // all h1(t-1) reads done
#pragma unroll
        for (int e = 0; e < 4; e++) {
            int u = u1 + (e & 1);
            int s = g + ((e & 2) ? 8 : 0);
            float h = lstm_cell(C1[0][e], C1[1][e], C1[2][e], C1[3][e], c1[e]);
            split_store(h1hi, h1lo, s * RS1 + u, h);
        }
        __syncthreads();  // h1(t) visible

        // ---- layer 2: z2 = h1@W2 + h2@U2 + b2 (K=192 split 96/96) ----
        float C2[4][4];
        if (kh == 0) {
#pragma unroll
            for (int gg = 0; gg < 4; gg++)
#pragma unroll
                for (int e = 0; e < 4; e++) C2[gg][e] = b2v[gg * 2 + (e & 1)];
            gemm_part<6, 12>(C2, g_wfrag + SEC_L2, 0, wl, 8, h1hi, h1lo, RS1, g, t);
        } else {
#pragma unroll
            for (int gg = 0; gg < 4; gg++)
#pragma unroll
                for (int e = 0; e < 4; e++) C2[gg][e] = 0.0f;
            gemm_part<2, 12>(C2, g_wfrag + SEC_L2, 6, wl, 8, h1hi + 96, h1lo + 96, RS1, g, t);
            gemm_part<4, 12>(C2, g_wfrag + SEC_L2, 8, wl, 8, h2hi, h2lo, RS2, g, t);
#pragma unroll
            for (int gg = 0; gg < 4; gg++)
#pragma unroll
                for (int e = 0; e < 4; e++)
                    pbuf[gg * 4 + e][wl * 32 + lane] = C2[gg][e];
        }
        __syncthreads();  // partials visible; all h1(t)/h2(t-1) reads done
        if (kh == 0) {
#pragma unroll
            for (int e = 0; e < 4; e++) {
                int u = u2 + (e & 1);
                int s = g + ((e & 2) ? 8 : 0);
                float zi = C2[0][e] + pbuf[0 * 4 + e][wl * 32 + lane];
                float zf = C2[1][e] + pbuf[1 * 4 + e][wl * 32 + lane];
                float zg = C2[2][e] + pbuf[2 * 4 + e][wl * 32 + lane];
                float zo = C2[3][e] + pbuf[3 * 4 + e][wl * 32 + lane];
                float h = lstm_cell(zi, zf, zg, zo, c2[e]);
                split_store(h2hi, h2lo, s * RS2 + u, h);
                if (tt == T_SEQ - 1) g_h2last[(b0 + s) * 64 + u] = h;
            }
        }
        // h2(t) writes vs next-step reads: separated by next step's 2 bars
    }
}

// ---------------------------------------------------------------------------
// Phase B: Repeat(h2last) -> LSTM3 (64) -> LSTM4 (128) -> Dense(1).
// L3: K=64 split 32/32; L4: full K, nb = gg*16 + w. Dense reduced via shfl
// over t-lanes then pd[16 warps][16 samples].
// ---------------------------------------------------------------------------
__global__ void __launch_bounds__(512, 1)
phaseB_kernel(const float* __restrict__ W3, const float* __restrict__ b3,
              const float* __restrict__ b4, const float* __restrict__ Wd,
              const float* __restrict__ bd, float* __restrict__ out) {
    __shared__ __half h3hi[16 * RS2], h3lo[16 * RS2];
    __shared__ __half h4hi[16 * RS1], h4lo[16 * RS1];
    __shared__ float h2s[16 * 66];
    __shared__ float pbuf[16][256];
    __shared__ float pd[256];

    const int tid = threadIdx.x;
    const int w = tid >> 5, lane = tid & 31, g = lane >> 2, t = lane & 3;
    const int wl = w & 7, kh = w >> 3;
    const int b0 = blockIdx.x * BT;

    for (int i = tid; i < BT * 64; i += 512) {
        int b = i >> 6, k = i & 63;
        h2s[b * 66 + k] = g_h2last[(b0 + b) * 64 + k];
    }
    for (int i = tid; i < 16 * RS2; i += 512) { h3hi[i] = __ushort_as_half(0); h3lo[i] = __ushort_as_half(0); }
    for (int i = tid; i < 16 * RS1; i += 512) { h4hi[i] = __ushort_as_half(0); h4lo[i] = __ushort_as_half(0); }

    const int u1 = 8 * w + 2 * t;   // layer-4 unit base
    const int u2 = 8 * wl + 2 * t;  // layer-3 unit base

    float b4v[8], wd0, wd1;
#pragma unroll
    for (int gg = 0; gg < 4; gg++)
#pragma unroll
        for (int e1 = 0; e1 < 2; e1++)
            b4v[gg * 2 + e1] = b4[gg * 128 + u1 + e1];
    wd0 = Wd[u1]; wd1 = Wd[u1 + 1];
    const float bdv = bd[0];

    __syncthreads();

    // zx3 = b3 + h2last @ W3 (fp32 exact, constant over t) — warps 0-7 use it
    float zx[4][4];
#pragma unroll
    for (int gg = 0; gg < 4; gg++)
#pragma unroll
        for (int e = 0; e < 4; e++) zx[gg][e] = b3[gg * 64 + u2 + (e & 1)];
    for (int k = 0; k < 64; k++) {
        float ha = h2s[g * 66 + k], hb = h2s[(g + 8) * 66 + k];
#pragma unroll
        for (int gg = 0; gg < 4; gg++) {
            float w0 = W3[k * 256 + gg * 64 + u2];
            float w1 = W3[k * 256 + gg * 64 + u2 + 1];
            zx[gg][0] = fmaf(ha, w0, zx[gg][0]);
            zx[gg][1] = fmaf(ha, w1, zx[gg][1]);
            zx[gg][2] = fmaf(hb, w0, zx[gg][2]);
            zx[gg][3] = fmaf(hb, w1, zx[gg][3]);
        }
    }

    float c3[4], c4[4];
#pragma unroll
    for (int j = 0; j < 4; j++) { c3[j] = 0.0f; c4[j] = 0.0f; }

    for (int tt = 0; tt < T_SEQ; tt++) {
        // ---- layer 3: z3 = zx3 + h3@U3 (K=64 split 32/32) ----
        float C3[4][4];
        if (kh == 0) {
#pragma unroll
            for (int gg = 0; gg < 4; gg++)
#pragma unroll
                for (int e = 0; e < 4; e++) C3[gg][e] = zx[gg][e];
            gemm_part<2, 4>(C3, g_wfrag + SEC_L3, 0, wl, 8, h3hi, h3lo, RS2, g, t);
        } else {
#pragma unroll
            for (int gg = 0; gg < 4; gg++)
#pragma unroll
                for (int e = 0; e < 4; e++) C3[gg][e] = 0.0f;
            gemm_part<2, 4>(C3, g_wfrag + SEC_L3, 2, wl, 8, h3hi + 32, h3lo + 32, RS2, g, t);
#pragma unroll
            for (int gg = 0; gg < 4; gg++)
#pragma unroll
                for (int e = 0; e < 4; e++)
                    pbuf[gg * 4 + e][wl * 32 + lane] = C3[gg][e];
        }
        __syncthreads();  // partials visible; h3(t-1) reads done
        if (kh == 0) {
#pragma unroll
            for (int e = 0; e < 4; e++) {
                int u = u2 + (e & 1);
                int s = g + ((e & 2) ? 8 : 0);
                float zi = C3[0][e] + pbuf[0 * 4 + e][wl * 32 + lane];
                float zf = C3[1][e] + pbuf[1 * 4 + e][wl * 32 + lane];
                float zg = C3[2][e] + pbuf[2 * 4 + e][wl * 32 + lane];
                float zo = C3[3][e] + pbuf[3 * 4 + e][wl * 32 + lane];
                float h = lstm_cell(zi, zf, zg, zo, c3[e]);
                split_store(h3hi, h3lo, s * RS2 + u, h);
            }
        }
        __syncthreads();  // h3(t) visible

        // ---- layer 4: z4 = h3@W4 + h4@U4 + b4 (full K per warp) ----
        float C4[4][4];
#pragma unroll
        for (int gg = 0; gg < 4; gg++)
#pragma unroll
            for (int e = 0; e < 4; e++) C4[gg][e] = b4v[gg * 2 + (e & 1)];
        gemm_part<4, 12>(C4, g_wfrag + SEC_L4, 0, w, 16, h3hi, h3lo, RS2, g, t);
        gemm_part<8, 12>(C4, g_wfrag + SEC_L4, 4, w, 16, h4hi, h4lo, RS1, g, t);
        __syncthreads();  // h4(t-1) + h3(t) reads done
        {
            float pA = 0.0f, pB = 0.0f;
#pragma unroll
            for (int e = 0; e < 4; e++) {
                int u = u1 + (e & 1);
                int s = g + ((e & 2) ? 8 : 0);
                float h = lstm_cell(C4[0][e], C4[1][e], C4[2][e], C4[3][e], c4[e]);
                split_store(h4hi, h4lo, s * RS1 + u, h);
                float wv = (e & 1) ? wd1 : wd0;
                if (e & 2) pB = fmaf(h, wv, pB);
                else       pA = fmaf(h, wv, pA);
            }
            pA += __shfl_xor_sync(0xffffffffu, pA, 1);
            pA += __shfl_xor_sync(0xffffffffu, pA, 2);
            pB += __shfl_xor_sync(0xffffffffu, pB, 1);
            pB += __shfl_xor_sync(0xffffffffu, pB, 2);
            if (t == 0) {
                pd[w * 16 + g] = pA;
                pd[w * 16 + 8 + g] = pB;
            }
        }
        __syncthreads();  // h4(t) + pd visible
        if (tid < 16) {
            float s_ = bdv;
#pragma unroll
            for (int wi = 0; wi < 16; wi++) s_ += pd[wi * 16 + tid];
            out[(b0 + tid) * T_SEQ + tt] = s_;
        }
        // pd rewritten only after next step's 3rd barrier -> safe
    }
}

// ---------------------------------------------------------------------------
extern "C" void kernel_launch(void* const* d_in, const int* in_sizes, int n_in,
                              void* d_out, int out_size) {
    const float* x  = (const float*)d_in[0];
    const float* W1 = (const float*)d_in[1];
    const float* U1 = (const float*)d_in[2];
    const float* b1 = (const float*)d_in[3];
    const float* W2 = (const float*)d_in[4];
    const float* U2 = (const float*)d_in[5];
    const float* b2 = (const float*)d_in[6];
    const float* W3 = (const float*)d_in[7];
    const float* U3 = (const float*)d_in[8];
    const float* b3 = (const float*)d_in[9];
    const float* W4 = (const float*)d_in[10];
    const float* U4 = (const float*)d_in[11];
    const float* b4 = (const float*)d_in[12];
    const float* Wd = (const float*)d_in[13];
    const float* bd = (const float*)d_in[14];
    float* out = (float*)d_out;

    pack_kernel<<<224, 256>>>(U1, W2, U2, U3, W4, U4);
    phaseA_kernel<<<NBLK, 512>>>(x, W1, b1, b2);
    phaseB_kernel<<<NBLK, 512>>>(W3, b3, b4, Wd, bd, out);
}